// round 1
// baseline (speedup 1.0000x reference)
#include <cuda_runtime.h>
#include <cstdint>
#include <cstddef>

// ---------------------------------------------------------------------------
// Problem constants
// ---------------------------------------------------------------------------
#define BB   32      // batch
#define NN   144     // seq len
#define EE   127     // embed size
#define DD   512     // encoding size
#define HH   8       // heads
#define DK   64
#define DV   64
#define FF   16384   // feed-forward dim
#define LL   4       // layers
#define MROWS (BB*NN)        // 4608
#define KENC  (EE+1)         // 513

// ---------------------------------------------------------------------------
// Scratch (static device globals; no dynamic allocation allowed)
// ---------------------------------------------------------------------------
__device__ float g_xp  [MROWS * KENC];   // x with PE channel appended
__device__ float g_xe  [MROWS * DD];     // encoder output
__device__ float g_cur [MROWS * DD];     // layer output
__device__ float g_q   [MROWS * DD];
__device__ float g_k   [MROWS * DD];
__device__ float g_v   [MROWS * DD];
__device__ float g_attn[MROWS * DD];
__device__ float g_a1  [MROWS * DD];
__device__ float g_qln [MROWS * DD];
__device__ float g_a2  [MROWS * DD];
__device__ float g_ff  [MROWS * DD];
__device__ float g_ao  [MROWS * DD];
__device__ float g_hid [MROWS * FF];     // FF hidden (288 MB)

// ---------------------------------------------------------------------------
// SGEMM: C[M,N] = A[M,K] @ B[K,N] + bias (opt ReLU)
// 128x128 block tile, 16 K-tile, 8x8 per thread, 256 threads.
// ---------------------------------------------------------------------------
#define BM 128
#define BN 128
#define BK 16

__global__ void __launch_bounds__(256)
sgemm_kernel(const float* __restrict__ A, const float* __restrict__ B,
             const float* __restrict__ bias, float* __restrict__ C,
             int M, int N, int K, int relu)
{
    __shared__ __align__(16) float As[BK][BM];
    __shared__ __align__(16) float Bs[BK][BN];

    const int tid = threadIdx.x;
    const int tx  = tid & 15;
    const int ty  = tid >> 4;
    const int bm  = blockIdx.y * BM;
    const int bn  = blockIdx.x * BN;

    float acc[8][8];
#pragma unroll
    for (int i = 0; i < 8; i++)
#pragma unroll
        for (int j = 0; j < 8; j++) acc[i][j] = 0.f;

    for (int k0 = 0; k0 < K; k0 += BK) {
        // Load A tile (BM x BK), store transposed As[k][m]
#pragma unroll
        for (int i = tid; i < BM * BK; i += 256) {
            int m  = i >> 4;
            int kk = i & 15;
            int gm = bm + m, gk = k0 + kk;
            As[kk][m] = (gm < M && gk < K) ? A[(size_t)gm * K + gk] : 0.f;
        }
        // Load B tile (BK x BN), coalesced on n
#pragma unroll
        for (int i = tid; i < BK * BN; i += 256) {
            int kk = i >> 7;
            int n  = i & 127;
            int gk = k0 + kk, gn = bn + n;
            Bs[kk][n] = (gk < K && gn < N) ? B[(size_t)gk * N + gn] : 0.f;
        }
        __syncthreads();

#pragma unroll
        for (int kk = 0; kk < BK; kk++) {
            float4 a0 = *(const float4*)&As[kk][ty * 4];
            float4 a1 = *(const float4*)&As[kk][ty * 4 + 64];
            float4 b0 = *(const float4*)&Bs[kk][tx * 4];
            float4 b1 = *(const float4*)&Bs[kk][tx * 4 + 64];
            float ar[8] = {a0.x, a0.y, a0.z, a0.w, a1.x, a1.y, a1.z, a1.w};
            float br[8] = {b0.x, b0.y, b0.z, b0.w, b1.x, b1.y, b1.z, b1.w};
#pragma unroll
            for (int i = 0; i < 8; i++)
#pragma unroll
                for (int j = 0; j < 8; j++)
                    acc[i][j] += ar[i] * br[j];
        }
        __syncthreads();
    }

    // Epilogue
#pragma unroll
    for (int i = 0; i < 8; i++) {
        int lm = (i < 4) ? (ty * 4 + i) : (64 + ty * 4 + i - 4);
        int gm = bm + lm;
        if (gm >= M) continue;
#pragma unroll
        for (int j = 0; j < 8; j++) {
            int ln = (j < 4) ? (tx * 4 + j) : (64 + tx * 4 + j - 4);
            int gn = bn + ln;
            if (gn >= N) continue;
            float val = acc[i][j];
            if (bias) val += bias[gn];
            if (relu) val = fmaxf(val, 0.f);
            C[(size_t)gm * N + gn] = val;
        }
    }
}

// ---------------------------------------------------------------------------
// Concat positional-encoding channel: xp[r, 0:127] = x[r,:], xp[r,127] = n/143
// ---------------------------------------------------------------------------
__global__ void concat_pe_kernel(const float* __restrict__ x, float* __restrict__ xp)
{
    int idx = blockIdx.x * 256 + threadIdx.x;
    if (idx >= MROWS * KENC) return;
    int row = idx / KENC;
    int c   = idx - row * KENC;
    float val;
    if (c < EE) val = x[(size_t)row * EE + c];
    else        val = (float)(row % NN) * (1.f / (float)(NN - 1));
    xp[idx] = val;
}

// ---------------------------------------------------------------------------
// Diagonal-softmax attention.
// For each (b,h,n): scores_m = q_n . k_m over valid m (m<=n if masked, else all);
// d = softmax(scores)[n]; out[b,n,h,:] = d * v[b,n,h,:].
// q,k,v,out layout: [b, n, h*64 + d] row-major (rows of 512).
// ---------------------------------------------------------------------------
__global__ void __launch_bounds__(256)
diag_attn_kernel(const float* __restrict__ q, const float* __restrict__ k,
                 const float* __restrict__ v, float* __restrict__ out, int masked)
{
    const int n = blockIdx.x;   // 0..143
    const int h = blockIdx.y;   // 0..7
    const int b = blockIdx.z;   // 0..31
    const int t = threadIdx.x;  // 0..255

    __shared__ float qs[DK];
    __shared__ float sc[256];
    __shared__ float red[256];

    const size_t rowbase = (size_t)(b * NN + n) * DD + h * DK;
    if (t < DK) qs[t] = q[rowbase + t];
    __syncthreads();

    const int mlim = masked ? (n + 1) : NN;
    float s = 0.f;
    if (t < mlim) {
        const float* kr = k + (size_t)(b * NN + t) * DD + h * DK;
#pragma unroll
        for (int d = 0; d < DK; d++) s += qs[d] * kr[d];
    }
    sc[t]  = s;
    red[t] = (t < mlim) ? s : -3.0e38f;
    __syncthreads();

    // max reduce
#pragma unroll
    for (int off = 128; off > 0; off >>= 1) {
        if (t < off) red[t] = fmaxf(red[t], red[t + off]);
        __syncthreads();
    }
    const float mx = red[0];
    __syncthreads();

    red[t] = (t < mlim) ? expf(sc[t] - mx) : 0.f;
    __syncthreads();
#pragma unroll
    for (int off = 128; off > 0; off >>= 1) {
        if (t < off) red[t] += red[t + off];
        __syncthreads();
    }
    const float denom = red[0];
    const float dcoef = expf(sc[n] - mx) / denom;

    if (t < DV) {
        out[rowbase + t] = dcoef * v[rowbase + t];
    }
}

// ---------------------------------------------------------------------------
// Fused residual add + LayerNorm over D=512. One block (256 threads) per row.
// out = LN(a + r) * g + beta
// ---------------------------------------------------------------------------
__global__ void __launch_bounds__(256)
add_ln_kernel(const float* __restrict__ a, const float* __restrict__ r,
              const float* __restrict__ g, const float* __restrict__ beta,
              float* __restrict__ out)
{
    const int row = blockIdx.x;
    const int t   = threadIdx.x;
    __shared__ float red[256];

    const size_t base = (size_t)row * DD;
    const float x0 = a[base + t]       + r[base + t];
    const float x1 = a[base + 256 + t] + r[base + 256 + t];

    red[t] = x0 + x1;
    __syncthreads();
#pragma unroll
    for (int off = 128; off > 0; off >>= 1) {
        if (t < off) red[t] += red[t + off];
        __syncthreads();
    }
    const float mean = red[0] * (1.f / (float)DD);
    __syncthreads();

    const float d0 = x0 - mean, d1 = x1 - mean;
    red[t] = d0 * d0 + d1 * d1;
    __syncthreads();
#pragma unroll
    for (int off = 128; off > 0; off >>= 1) {
        if (t < off) red[t] += red[t + off];
        __syncthreads();
    }
    const float inv = rsqrtf(red[0] * (1.f / (float)DD) + 1e-5f);

    out[base + t]       = d0 * inv * g[t]       + beta[t];
    out[base + 256 + t] = d1 * inv * g[256 + t] + beta[256 + t];
}

// ---------------------------------------------------------------------------
// Host orchestration
// ---------------------------------------------------------------------------
static inline void launch_gemm(const float* A, const float* B, const float* bias,
                               float* C, int M, int N, int K, int relu)
{
    dim3 grid((N + BN - 1) / BN, (M + BM - 1) / BM);
    sgemm_kernel<<<grid, 256>>>(A, B, bias, C, M, N, K, relu);
}

extern "C" void kernel_launch(void* const* d_in, const int* in_sizes, int n_in,
                              void* d_out, int out_size)
{
    // Inputs (metadata order):
    // 0 batch_size, 1 x, 2 future_mask(ignored), 3 Wenc, 4 benc,
    // 5 Wq, 6 Wk, 7 Wv, 8 Wo, 9 bo,
    // 10 ln1_g, 11 ln1_b, 12 ln2_g, 13 ln2_b, 14 ln3_g, 15 ln3_b,
    // 16 W1, 17 b1, 18 W2, 19 b2, 20 Wdec, 21 bdec
    const float* x    = (const float*)d_in[1];
    const float* Wenc = (const float*)d_in[3];
    const float* benc = (const float*)d_in[4];
    const float* Wq   = (const float*)d_in[5];
    const float* Wk   = (const float*)d_in[6];
    const float* Wv   = (const float*)d_in[7];
    const float* Wo   = (const float*)d_in[8];
    const float* bo   = (const float*)d_in[9];
    const float* ln1g = (const float*)d_in[10];
    const float* ln1b = (const float*)d_in[11];
    const float* ln2g = (const float*)d_in[12];
    const float* ln2b = (const float*)d_in[13];
    const float* ln3g = (const float*)d_in[14];
    const float* ln3b = (const float*)d_in[15];
    const float* W1   = (const float*)d_in[16];
    const float* b1   = (const float*)d_in[17];
    const float* W2   = (const float*)d_in[18];
    const float* b2   = (const float*)d_in[19];
    const float* Wdec = (const float*)d_in[20];
    const float* bdec = (const float*)d_in[21];

    float *p_xp, *p_xe, *p_cur, *p_q, *p_k, *p_v, *p_attn, *p_a1, *p_qln,
          *p_a2, *p_ff, *p_ao, *p_hid;
    cudaGetSymbolAddress((void**)&p_xp,   g_xp);
    cudaGetSymbolAddress((void**)&p_xe,   g_xe);
    cudaGetSymbolAddress((void**)&p_cur,  g_cur);
    cudaGetSymbolAddress((void**)&p_q,    g_q);
    cudaGetSymbolAddress((void**)&p_k,    g_k);
    cudaGetSymbolAddress((void**)&p_v,    g_v);
    cudaGetSymbolAddress((void**)&p_attn, g_attn);
    cudaGetSymbolAddress((void**)&p_a1,   g_a1);
    cudaGetSymbolAddress((void**)&p_qln,  g_qln);
    cudaGetSymbolAddress((void**)&p_a2,   g_a2);
    cudaGetSymbolAddress((void**)&p_ff,   g_ff);
    cudaGetSymbolAddress((void**)&p_ao,   g_ao);
    cudaGetSymbolAddress((void**)&p_hid,  g_hid);

    // --- Encoder: xe = concat(x, pe) @ Wenc + benc ---
    {
        int tot = MROWS * KENC;
        concat_pe_kernel<<<(tot + 255) / 256, 256>>>(x, p_xp);
        launch_gemm(p_xp, Wenc, benc, p_xe, MROWS, DD, KENC, 0);
    }

    dim3 attn_grid(NN, HH, BB);

    for (int l = 0; l < LL; l++) {
        const float* cur_in = (l == 0) ? p_xe : p_cur;
        const float* Wql = Wq + (size_t)l * DD * DD;
        const float* Wkl = Wk + (size_t)l * DD * DD;
        const float* Wvl = Wv + (size_t)l * DD * DD;
        const float* Wol = Wo + (size_t)l * DD * DD;
        const float* bol = bo + (size_t)l * DD;
        const float* W1l = W1 + (size_t)l * DD * FF;
        const float* b1l = b1 + (size_t)l * FF;
        const float* W2l = W2 + (size_t)l * FF * DD;
        const float* b2l = b2 + (size_t)l * DD;

        // --- MHA1: self-attention on cur_in, causal mask ---
        launch_gemm(cur_in, Wql, nullptr, p_q, MROWS, DD, DD, 0);
        launch_gemm(cur_in, Wkl, nullptr, p_k, MROWS, DD, DD, 0);
        launch_gemm(cur_in, Wvl, nullptr, p_v, MROWS, DD, DD, 0);
        diag_attn_kernel<<<attn_grid, 256>>>(p_q, p_k, p_v, p_attn, 1);
        launch_gemm(p_attn, Wol, bol, p_a1, MROWS, DD, DD, 0);

        // q = LN(a1 + xe)
        add_ln_kernel<<<MROWS, 256>>>(p_a1, p_xe,
                                      ln1g + (size_t)l * DD, ln1b + (size_t)l * DD, p_qln);

        // --- MHA2: K,V from xe, Q from qln, no mask ---
        launch_gemm(p_qln, Wql, nullptr, p_q, MROWS, DD, DD, 0);
        launch_gemm(p_xe,  Wkl, nullptr, p_k, MROWS, DD, DD, 0);
        launch_gemm(p_xe,  Wvl, nullptr, p_v, MROWS, DD, DD, 0);
        diag_attn_kernel<<<attn_grid, 256>>>(p_q, p_k, p_v, p_attn, 0);
        launch_gemm(p_attn, Wol, bol, p_a2, MROWS, DD, DD, 0);

        // --- FF stack 1: ff = relu(a2 @ W1 + b1) @ W2 + b2 ; ao = LN(ff + a2) ---
        launch_gemm(p_a2,  W1l, b1l, p_hid, MROWS, FF, DD, 1);
        launch_gemm(p_hid, W2l, b2l, p_ff,  MROWS, DD, FF, 0);
        add_ln_kernel<<<MROWS, 256>>>(p_ff, p_a2,
                                      ln2g + (size_t)l * DD, ln2b + (size_t)l * DD, p_ao);

        // --- FF stack 2: ff2 = relu(ao @ W1 + b1) @ W2 + b2 ; out = LN(ao + ff2) ---
        launch_gemm(p_ao,  W1l, b1l, p_hid, MROWS, FF, DD, 1);
        launch_gemm(p_hid, W2l, b2l, p_ff,  MROWS, DD, FF, 0);
        add_ln_kernel<<<MROWS, 256>>>(p_ff, p_ao,
                                      ln3g + (size_t)l * DD, ln3b + (size_t)l * DD, p_cur);
    }

    // --- Decoder: out = cur @ Wdec + bdec ---
    launch_gemm(p_cur, Wdec, bdec, (float*)d_out, MROWS, EE, DD, 0);
}

// round 3
// speedup vs baseline: 2.3982x; 2.3982x over previous
#include <cuda_runtime.h>
#include <cuda_bf16.h>
#include <cstdint>
#include <cstddef>

// ---------------------------------------------------------------------------
// Problem constants
// ---------------------------------------------------------------------------
#define BB   32
#define NN   144
#define EE   127
#define DD   512
#define HH   8
#define DK   64
#define DV   64
#define FF   16384
#define LL   4
#define MROWS (BB*NN)        // 4608
#define KENC  (EE+1)         // 513

// ---------------------------------------------------------------------------
// Scratch (static device globals)
// ---------------------------------------------------------------------------
__device__ float g_xp  [MROWS * KENC];
__device__ float g_xe  [MROWS * DD];
__device__ float g_cur [MROWS * DD];
__device__ float g_q   [MROWS * DD];
__device__ float g_k   [MROWS * DD];
__device__ float g_v   [MROWS * DD];
__device__ float g_attn[MROWS * DD];
__device__ float g_a1  [MROWS * DD];
__device__ float g_qln [MROWS * DD];
__device__ float g_a2  [MROWS * DD];
__device__ float g_ff  [MROWS * DD];
__device__ float g_ao  [MROWS * DD];
__device__ float g_hid [MROWS * FF];

// Transposed + hi/lo-split bf16 weights: [N,K] row-major per layer
__device__ __nv_bfloat16 g_wqT_h[LL*DD*DD], g_wqT_l[LL*DD*DD];
__device__ __nv_bfloat16 g_wkT_h[LL*DD*DD], g_wkT_l[LL*DD*DD];
__device__ __nv_bfloat16 g_wvT_h[LL*DD*DD], g_wvT_l[LL*DD*DD];
__device__ __nv_bfloat16 g_woT_h[LL*DD*DD], g_woT_l[LL*DD*DD];
__device__ __nv_bfloat16 g_w1T_h[(size_t)LL*FF*DD], g_w1T_l[(size_t)LL*FF*DD];
__device__ __nv_bfloat16 g_w2T_h[(size_t)LL*DD*FF], g_w2T_l[(size_t)LL*DD*FF];

// ---------------------------------------------------------------------------
// Small helpers
// ---------------------------------------------------------------------------
__device__ __forceinline__ uint32_t smem_u32(const void* p) {
    uint32_t a;
    asm("{ .reg .u64 t; cvta.to.shared.u64 t, %1; cvt.u32.u64 %0, t; }" : "=r"(a) : "l"(p));
    return a;
}
__device__ __forceinline__ uint32_t bfpack(float x, float y) {
    __nv_bfloat162 t = __floats2bfloat162_rn(x, y);
    return *reinterpret_cast<uint32_t*>(&t);
}
__device__ __forceinline__ void sts16(uint32_t a, uint32_t u0, uint32_t u1,
                                      uint32_t u2, uint32_t u3) {
    asm volatile("st.shared.v4.b32 [%0], {%1, %2, %3, %4};"
                 :: "r"(a), "r"(u0), "r"(u1), "r"(u2), "r"(u3) : "memory");
}
__device__ __forceinline__ void cpa16(uint32_t d, const void* s) {
    asm volatile("cp.async.cg.shared.global [%0], [%1], 16;" :: "r"(d), "l"(s));
}
__device__ __forceinline__ void cpa_commit() {
    asm volatile("cp.async.commit_group;" ::: "memory");
}
__device__ __forceinline__ void ldsm4(uint32_t a, uint32_t& r0, uint32_t& r1,
                                      uint32_t& r2, uint32_t& r3) {
    asm volatile("ldmatrix.sync.aligned.m8n8.x4.shared.b16 {%0,%1,%2,%3}, [%4];"
                 : "=r"(r0), "=r"(r1), "=r"(r2), "=r"(r3) : "r"(a));
}
__device__ __forceinline__ void mma16816(float* c, const uint32_t* a,
                                         uint32_t b0, uint32_t b1) {
    asm volatile("mma.sync.aligned.m16n8k16.row.col.f32.bf16.bf16.f32 "
                 "{%0,%1,%2,%3},{%4,%5,%6,%7},{%8,%9},{%0,%1,%2,%3};"
                 : "+f"(c[0]), "+f"(c[1]), "+f"(c[2]), "+f"(c[3])
                 : "r"(a[0]), "r"(a[1]), "r"(a[2]), "r"(a[3]), "r"(b0), "r"(b1));
}

// ---------------------------------------------------------------------------
// HMMA split-bf16 GEMM: C[M,N] = A[M,K](fp32) @ B[K,N]
// B pre-transposed as Bh/Bl [N,K] bf16 (hi/lo split). A split on the fly.
// Block tile 128x128, BK=32, 256 threads (8 warps: 2M x 4N), warp tile 64x32.
// Requires M%128==0, N%128==0, K%32==0.
// ---------------------------------------------------------------------------
#define SA   40                 // smem row stride (elems): 80B -> ldmatrix conflict-free
#define STGB (128 * SA * 2)     // bytes per tile buffer = 10240
#define HMMA_SMEM (8 * STGB)    // Ah/Al/Bh/Bl x 2 stages = 81920

__global__ void __launch_bounds__(256, 1)
hmma_gemm(const float* __restrict__ A,
          const __nv_bfloat16* __restrict__ Bh,
          const __nv_bfloat16* __restrict__ Bl,
          const float* __restrict__ bias,
          float* __restrict__ C,
          int M, int N, int K, int relu)
{
    extern __shared__ __nv_bfloat16 smraw[];
    const uint32_t sb = smem_u32(smraw);
    // buffer offsets: AH[2], AL[2], BH[2], BL[2]
    const uint32_t OF_AH = 0, OF_AL = 2 * STGB, OF_BH = 4 * STGB, OF_BL = 6 * STGB;

    const int tid  = threadIdx.x;
    const int lane = tid & 31;
    const int wid  = tid >> 5;
    const int wm   = wid >> 2;        // 0..1
    const int wn   = wid & 3;         // 0..3
    const int bm   = blockIdx.y * 128;
    const int bn   = blockIdx.x * 128;

    // A staging: thread covers row=tid>>1, 16 cols at (tid&1)*16
    const int arow = tid >> 1;
    const int acol = (tid & 1) * 16;
    const float* Ap = A + (size_t)(bm + arow) * K + acol;
    const uint32_t a_sts = (uint32_t)(arow * SA + acol) * 2;

    // B staging: thread covers row=tid>>1, two 16B segs starting at seg=(tid&1)*2
    const int brow = tid >> 1;
    const int bseg = (tid & 1) * 2;
    const __nv_bfloat16* Bhp = Bh + (size_t)(bn + brow) * K + bseg * 8;
    const __nv_bfloat16* Blp = Bl + (size_t)(bn + brow) * K + bseg * 8;
    const uint32_t b_sts = (uint32_t)(brow * SA) * 2 + bseg * 16;

    // ldmatrix lane addressing
    const int r  = lane & 7;
    const int q1 = (lane >> 3) & 1;
    const int q2 = lane >> 4;
    // A frag: row = wm*64 + mi*16 + q1*8 + r ; k = ks*16 + q2*8
    const uint32_t oa = (uint32_t)((wm * 64 + q1 * 8 + r) * SA + q2 * 8) * 2;
    // B frag: n = wn*32 + p*16 + q2*8 + r ; k = ks*16 + q1*8
    const uint32_t ob = (uint32_t)((wn * 32 + q2 * 8 + r) * SA + q1 * 8) * 2;

    float acc[4][4][4];
#pragma unroll
    for (int i = 0; i < 4; i++)
#pragma unroll
        for (int j = 0; j < 4; j++)
#pragma unroll
            for (int t = 0; t < 4; t++) acc[i][j][t] = 0.f;

    const int niter = K / 32;

    float4 ar[4];

    // ---- prologue: B(0) -> stage0 ; A(0) -> regs ----
    {
        const uint32_t dh = sb + OF_BH + b_sts;
        const uint32_t dl = sb + OF_BL + b_sts;
        cpa16(dh,      Bhp);
        cpa16(dh + 16, Bhp + 8);
        cpa16(dl,      Blp);
        cpa16(dl + 16, Blp + 8);
        cpa_commit();
#pragma unroll
        for (int j = 0; j < 4; j++) ar[j] = *(const float4*)(Ap + j * 4);
    }

    for (int i = 0; i < niter; i++) {
        const int s = i & 1;
        const uint32_t so = (uint32_t)s * STGB;

        // ---- STS A(i): convert fp32 -> bf16 hi/lo ----
        {
            float v[16];
#pragma unroll
            for (int j = 0; j < 4; j++) {
                v[j * 4 + 0] = ar[j].x; v[j * 4 + 1] = ar[j].y;
                v[j * 4 + 2] = ar[j].z; v[j * 4 + 3] = ar[j].w;
            }
            uint32_t hi[8], lo[8];
#pragma unroll
            for (int j = 0; j < 8; j++) {
                float x = v[2 * j], y = v[2 * j + 1];
                __nv_bfloat16 hx = __float2bfloat16_rn(x);
                __nv_bfloat16 hy = __float2bfloat16_rn(y);
                hi[j] = bfpack(__bfloat162float(hx), __bfloat162float(hy)); // exact repack
                lo[j] = bfpack(x - __bfloat162float(hx), y - __bfloat162float(hy));
            }
            const uint32_t dah = sb + OF_AH + so + a_sts;
            const uint32_t dal = sb + OF_AL + so + a_sts;
            sts16(dah,      hi[0], hi[1], hi[2], hi[3]);
            sts16(dah + 16, hi[4], hi[5], hi[6], hi[7]);
            sts16(dal,      lo[0], lo[1], lo[2], lo[3]);
            sts16(dal + 16, lo[4], lo[5], lo[6], lo[7]);
        }

        // ---- issue next-iter loads ----
        if (i + 1 < niter) {
            const uint32_t so1 = (uint32_t)((i + 1) & 1) * STGB;
            const uint32_t dh = sb + OF_BH + so1 + b_sts;
            const uint32_t dl = sb + OF_BL + so1 + b_sts;
            const __nv_bfloat16* bh = Bhp + (size_t)(i + 1) * 32;
            const __nv_bfloat16* bl = Blp + (size_t)(i + 1) * 32;
            cpa16(dh,      bh);
            cpa16(dh + 16, bh + 8);
            cpa16(dl,      bl);
            cpa16(dl + 16, bl + 8);
            cpa_commit();
            const float* ap = Ap + (size_t)(i + 1) * 32;
#pragma unroll
            for (int j = 0; j < 4; j++) ar[j] = *(const float4*)(ap + j * 4);
            asm volatile("cp.async.wait_group 1;" ::: "memory");
        } else {
            asm volatile("cp.async.wait_group 0;" ::: "memory");
        }
        __syncthreads();

        // ---- compute stage s: 2 k16 steps x 3 passes x 16 mma ----
#pragma unroll
        for (int ks = 0; ks < 2; ks++) {
            const uint32_t ko = (uint32_t)ks * 32;  // 16 elems * 2B
            uint32_t ah[4][4], al[4][4], bhf[2][4], blf[2][4];
#pragma unroll
            for (int mi = 0; mi < 4; mi++) {
                const uint32_t aoff = oa + (uint32_t)(mi * 16 * SA) * 2 + ko;
                ldsm4(sb + OF_AH + so + aoff, ah[mi][0], ah[mi][1], ah[mi][2], ah[mi][3]);
                ldsm4(sb + OF_AL + so + aoff, al[mi][0], al[mi][1], al[mi][2], al[mi][3]);
            }
#pragma unroll
            for (int p = 0; p < 2; p++) {
                const uint32_t boff = ob + (uint32_t)(p * 16 * SA) * 2 + ko;
                ldsm4(sb + OF_BH + so + boff, bhf[p][0], bhf[p][1], bhf[p][2], bhf[p][3]);
                ldsm4(sb + OF_BL + so + boff, blf[p][0], blf[p][1], blf[p][2], blf[p][3]);
            }
#pragma unroll
            for (int mi = 0; mi < 4; mi++)
#pragma unroll
                for (int ni = 0; ni < 4; ni++) {
                    const int p = ni >> 1, e = (ni & 1) * 2;
                    mma16816(acc[mi][ni], ah[mi], bhf[p][e], bhf[p][e + 1]);
                }
#pragma unroll
            for (int mi = 0; mi < 4; mi++)
#pragma unroll
                for (int ni = 0; ni < 4; ni++) {
                    const int p = ni >> 1, e = (ni & 1) * 2;
                    mma16816(acc[mi][ni], ah[mi], blf[p][e], blf[p][e + 1]);
                }
#pragma unroll
            for (int mi = 0; mi < 4; mi++)
#pragma unroll
                for (int ni = 0; ni < 4; ni++) {
                    const int p = ni >> 1, e = (ni & 1) * 2;
                    mma16816(acc[mi][ni], al[mi], bhf[p][e], bhf[p][e + 1]);
                }
        }
        __syncthreads();
    }

    // ---- epilogue ----
    const int erow = lane >> 2;
    const int ecol = (lane & 3) * 2;
#pragma unroll
    for (int mi = 0; mi < 4; mi++) {
        const int gr = bm + wm * 64 + mi * 16 + erow;
#pragma unroll
        for (int ni = 0; ni < 4; ni++) {
            const int gc = bn + wn * 32 + ni * 8 + ecol;
            float2 v0 = make_float2(acc[mi][ni][0], acc[mi][ni][1]);
            float2 v1 = make_float2(acc[mi][ni][2], acc[mi][ni][3]);
            if (bias) {
                float bx = bias[gc], by = bias[gc + 1];
                v0.x += bx; v0.y += by; v1.x += bx; v1.y += by;
            }
            if (relu) {
                v0.x = fmaxf(v0.x, 0.f); v0.y = fmaxf(v0.y, 0.f);
                v1.x = fmaxf(v1.x, 0.f); v1.y = fmaxf(v1.y, 0.f);
            }
            *(float2*)(C + (size_t)gr * N + gc)       = v0;
            *(float2*)(C + (size_t)(gr + 8) * N + gc) = v1;
        }
    }
}

// ---------------------------------------------------------------------------
// Weight transpose + hi/lo bf16 split: W[K,N] fp32 -> Th/Tl [N,K] bf16.
// ---------------------------------------------------------------------------
__global__ void wconv_kernel(const float* __restrict__ W,
                             __nv_bfloat16* __restrict__ Th,
                             __nv_bfloat16* __restrict__ Tl,
                             int K, int N)
{
    __shared__ float t[32][33];
    const size_t zoff = (size_t)blockIdx.z * K * N;
    const float* Wz = W + zoff;
    __nv_bfloat16* Thz = Th + zoff;
    __nv_bfloat16* Tlz = Tl + zoff;
    const int n0 = blockIdx.x * 32, k0 = blockIdx.y * 32;
    const int tx = threadIdx.x, ty = threadIdx.y;
#pragma unroll
    for (int i = 0; i < 32; i += 8)
        t[ty + i][tx] = Wz[(size_t)(k0 + ty + i) * N + n0 + tx];
    __syncthreads();
#pragma unroll
    for (int i = 0; i < 32; i += 8) {
        float f = t[tx][ty + i];
        __nv_bfloat16 h = __float2bfloat16_rn(f);
        __nv_bfloat16 l = __float2bfloat16_rn(f - __bfloat162float(h));
        size_t o = (size_t)(n0 + ty + i) * K + k0 + tx;
        Thz[o] = h; Tlz[o] = l;
    }
}

// ---------------------------------------------------------------------------
// Fallback fp32 SGEMM (encoder K=513, decoder N=127)
// ---------------------------------------------------------------------------
#define BM 128
#define BN 128
#define BK 16

__global__ void __launch_bounds__(256)
sgemm_kernel(const float* __restrict__ A, const float* __restrict__ B,
             const float* __restrict__ bias, float* __restrict__ C,
             int M, int N, int K, int relu)
{
    __shared__ __align__(16) float As[BK][BM];
    __shared__ __align__(16) float Bs[BK][BN];

    const int tid = threadIdx.x;
    const int tx = tid & 15, ty = tid >> 4;
    const int bm = blockIdx.y * BM, bn = blockIdx.x * BN;

    float acc[8][8];
#pragma unroll
    for (int i = 0; i < 8; i++)
#pragma unroll
        for (int j = 0; j < 8; j++) acc[i][j] = 0.f;

    for (int k0 = 0; k0 < K; k0 += BK) {
#pragma unroll
        for (int i = tid; i < BM * BK; i += 256) {
            int m = i >> 4, kk = i & 15;
            int gm = bm + m, gk = k0 + kk;
            As[kk][m] = (gm < M && gk < K) ? A[(size_t)gm * K + gk] : 0.f;
        }
#pragma unroll
        for (int i = tid; i < BK * BN; i += 256) {
            int kk = i >> 7, n = i & 127;
            int gk = k0 + kk, gn = bn + n;
            Bs[kk][n] = (gk < K && gn < N) ? B[(size_t)gk * N + gn] : 0.f;
        }
        __syncthreads();
#pragma unroll
        for (int kk = 0; kk < BK; kk++) {
            float4 a0 = *(const float4*)&As[kk][ty * 4];
            float4 a1 = *(const float4*)&As[kk][ty * 4 + 64];
            float4 b0 = *(const float4*)&Bs[kk][tx * 4];
            float4 b1 = *(const float4*)&Bs[kk][tx * 4 + 64];
            float arr[8] = {a0.x, a0.y, a0.z, a0.w, a1.x, a1.y, a1.z, a1.w};
            float brr[8] = {b0.x, b0.y, b0.z, b0.w, b1.x, b1.y, b1.z, b1.w};
#pragma unroll
            for (int i = 0; i < 8; i++)
#pragma unroll
                for (int j = 0; j < 8; j++)
                    acc[i][j] += arr[i] * brr[j];
        }
        __syncthreads();
    }
#pragma unroll
    for (int i = 0; i < 8; i++) {
        int lm = (i < 4) ? (ty * 4 + i) : (64 + ty * 4 + i - 4);
        int gm = bm + lm;
        if (gm >= M) continue;
#pragma unroll
        for (int j = 0; j < 8; j++) {
            int ln = (j < 4) ? (tx * 4 + j) : (64 + tx * 4 + j - 4);
            int gn = bn + ln;
            if (gn >= N) continue;
            float val = acc[i][j];
            if (bias) val += bias[gn];
            if (relu) val = fmaxf(val, 0.f);
            C[(size_t)gm * N + gn] = val;
        }
    }
}

// ---------------------------------------------------------------------------
// Positional-encoding concat
// ---------------------------------------------------------------------------
__global__ void concat_pe_kernel(const float* __restrict__ x, float* __restrict__ xp)
{
    int idx = blockIdx.x * 256 + threadIdx.x;
    if (idx >= MROWS * KENC) return;
    int row = idx / KENC;
    int c = idx - row * KENC;
    float val;
    if (c < EE) val = x[(size_t)row * EE + c];
    else        val = (float)(row % NN) * (1.f / (float)(NN - 1));
    xp[idx] = val;
}

// ---------------------------------------------------------------------------
// Diagonal-softmax attention
// ---------------------------------------------------------------------------
__global__ void __launch_bounds__(256)
diag_attn_kernel(const float* __restrict__ q, const float* __restrict__ k,
                 const float* __restrict__ v, float* __restrict__ out, int masked)
{
    const int n = blockIdx.x, h = blockIdx.y, b = blockIdx.z;
    const int t = threadIdx.x;

    __shared__ float qs[DK];
    __shared__ float sc[256];
    __shared__ float red[256];

    const size_t rowbase = (size_t)(b * NN + n) * DD + h * DK;
    if (t < DK) qs[t] = q[rowbase + t];
    __syncthreads();

    const int mlim = masked ? (n + 1) : NN;
    float s = 0.f;
    if (t < mlim) {
        const float* kr = k + (size_t)(b * NN + t) * DD + h * DK;
#pragma unroll
        for (int d = 0; d < DK; d++) s += qs[d] * kr[d];
    }
    sc[t] = s;
    red[t] = (t < mlim) ? s : -3.0e38f;
    __syncthreads();
#pragma unroll
    for (int off = 128; off > 0; off >>= 1) {
        if (t < off) red[t] = fmaxf(red[t], red[t + off]);
        __syncthreads();
    }
    const float mx = red[0];
    __syncthreads();
    red[t] = (t < mlim) ? expf(sc[t] - mx) : 0.f;
    __syncthreads();
#pragma unroll
    for (int off = 128; off > 0; off >>= 1) {
        if (t < off) red[t] += red[t + off];
        __syncthreads();
    }
    const float denom = red[0];
    const float dcoef = expf(sc[n] - mx) / denom;

    if (t < DV) out[rowbase + t] = dcoef * v[rowbase + t];
}

// ---------------------------------------------------------------------------
// Fused residual add + LayerNorm (D=512)
// ---------------------------------------------------------------------------
__global__ void __launch_bounds__(256)
add_ln_kernel(const float* __restrict__ a, const float* __restrict__ r,
              const float* __restrict__ g, const float* __restrict__ beta,
              float* __restrict__ out)
{
    const int row = blockIdx.x;
    const int t = threadIdx.x;
    __shared__ float red[256];

    const size_t base = (size_t)row * DD;
    const float x0 = a[base + t] + r[base + t];
    const float x1 = a[base + 256 + t] + r[base + 256 + t];

    red[t] = x0 + x1;
    __syncthreads();
#pragma unroll
    for (int off = 128; off > 0; off >>= 1) {
        if (t < off) red[t] += red[t + off];
        __syncthreads();
    }
    const float mean = red[0] * (1.f / (float)DD);
    __syncthreads();
    const float d0 = x0 - mean, d1 = x1 - mean;
    red[t] = d0 * d0 + d1 * d1;
    __syncthreads();
#pragma unroll
    for (int off = 128; off > 0; off >>= 1) {
        if (t < off) red[t] += red[t + off];
        __syncthreads();
    }
    const float inv = rsqrtf(red[0] * (1.f / (float)DD) + 1e-5f);

    out[base + t]       = d0 * inv * g[t]       + beta[t];
    out[base + 256 + t] = d1 * inv * g[256 + t] + beta[256 + t];
}

// ---------------------------------------------------------------------------
// Host orchestration
// ---------------------------------------------------------------------------
static inline void launch_sgemm(const float* A, const float* B, const float* bias,
                                float* C, int M, int N, int K, int relu)
{
    dim3 grid((N + BN - 1) / BN, (M + BM - 1) / BM);
    sgemm_kernel<<<grid, 256>>>(A, B, bias, C, M, N, K, relu);
}

static inline void launch_hgemm(const float* A, const __nv_bfloat16* Bh,
                                const __nv_bfloat16* Bl, const float* bias,
                                float* C, int M, int N, int K, int relu)
{
    dim3 grid(N / 128, M / 128);
    hmma_gemm<<<grid, 256, HMMA_SMEM>>>(A, Bh, Bl, bias, C, M, N, K, relu);
}

extern "C" void kernel_launch(void* const* d_in, const int* in_sizes, int n_in,
                              void* d_out, int out_size)
{
    const float* x    = (const float*)d_in[1];
    const float* Wenc = (const float*)d_in[3];
    const float* benc = (const float*)d_in[4];
    const float* Wq   = (const float*)d_in[5];
    const float* Wk   = (const float*)d_in[6];
    const float* Wv   = (const float*)d_in[7];
    const float* Wo   = (const float*)d_in[8];
    const float* bo   = (const float*)d_in[9];
    const float* ln1g = (const float*)d_in[10];
    const float* ln1b = (const float*)d_in[11];
    const float* ln2g = (const float*)d_in[12];
    const float* ln2b = (const float*)d_in[13];
    const float* ln3g = (const float*)d_in[14];
    const float* ln3b = (const float*)d_in[15];
    const float* W1   = (const float*)d_in[16];
    const float* b1   = (const float*)d_in[17];
    const float* W2   = (const float*)d_in[18];
    const float* b2   = (const float*)d_in[19];
    const float* Wdec = (const float*)d_in[20];
    const float* bdec = (const float*)d_in[21];

    float *p_xp, *p_xe, *p_cur, *p_q, *p_k, *p_v, *p_attn, *p_a1, *p_qln,
          *p_a2, *p_ff, *p_ao, *p_hid;
    cudaGetSymbolAddress((void**)&p_xp,   g_xp);
    cudaGetSymbolAddress((void**)&p_xe,   g_xe);
    cudaGetSymbolAddress((void**)&p_cur,  g_cur);
    cudaGetSymbolAddress((void**)&p_q,    g_q);
    cudaGetSymbolAddress((void**)&p_k,    g_k);
    cudaGetSymbolAddress((void**)&p_v,    g_v);
    cudaGetSymbolAddress((void**)&p_attn, g_attn);
    cudaGetSymbolAddress((void**)&p_a1,   g_a1);
    cudaGetSymbolAddress((void**)&p_qln,  g_qln);
    cudaGetSymbolAddress((void**)&p_a2,   g_a2);
    cudaGetSymbolAddress((void**)&p_ff,   g_ff);
    cudaGetSymbolAddress((void**)&p_ao,   g_ao);
    cudaGetSymbolAddress((void**)&p_hid,  g_hid);

    __nv_bfloat16 *wq_h, *wq_l, *wk_h, *wk_l, *wv_h, *wv_l, *wo_h, *wo_l,
                  *w1_h, *w1_l, *w2_h, *w2_l;
    cudaGetSymbolAddress((void**)&wq_h, g_wqT_h);
    cudaGetSymbolAddress((void**)&wq_l, g_wqT_l);
    cudaGetSymbolAddress((void**)&wk_h, g_wkT_h);
    cudaGetSymbolAddress((void**)&wk_l, g_wkT_l);
    cudaGetSymbolAddress((void**)&wv_h, g_wvT_h);
    cudaGetSymbolAddress((void**)&wv_l, g_wvT_l);
    cudaGetSymbolAddress((void**)&wo_h, g_woT_h);
    cudaGetSymbolAddress((void**)&wo_l, g_woT_l);
    cudaGetSymbolAddress((void**)&w1_h, g_w1T_h);
    cudaGetSymbolAddress((void**)&w1_l, g_w1T_l);
    cudaGetSymbolAddress((void**)&w2_h, g_w2T_h);
    cudaGetSymbolAddress((void**)&w2_l, g_w2T_l);

    cudaFuncSetAttribute(hmma_gemm, cudaFuncAttributeMaxDynamicSharedMemorySize, HMMA_SMEM);

    // --- Weight transpose + bf16 hi/lo split ---
    {
        dim3 wb(32, 8);
        wconv_kernel<<<dim3(DD / 32, DD / 32, LL), wb>>>(Wq, wq_h, wq_l, DD, DD);
        wconv_kernel<<<dim3(DD / 32, DD / 32, LL), wb>>>(Wk, wk_h, wk_l, DD, DD);
        wconv_kernel<<<dim3(DD / 32, DD / 32, LL), wb>>>(Wv, wv_h, wv_l, DD, DD);
        wconv_kernel<<<dim3(DD / 32, DD / 32, LL), wb>>>(Wo, wo_h, wo_l, DD, DD);
        wconv_kernel<<<dim3(FF / 32, DD / 32, LL), wb>>>(W1, w1_h, w1_l, DD, FF);
        wconv_kernel<<<dim3(DD / 32, FF / 32, LL), wb>>>(W2, w2_h, w2_l, FF, DD);
    }

    // --- Encoder ---
    {
        int tot = MROWS * KENC;
        concat_pe_kernel<<<(tot + 255) / 256, 256>>>(x, p_xp);
        launch_sgemm(p_xp, Wenc, benc, p_xe, MROWS, DD, KENC, 0);
    }

    dim3 attn_grid(NN, HH, BB);

    for (int l = 0; l < LL; l++) {
        const float* cur_in = (l == 0) ? p_xe : p_cur;
        const size_t wqo = (size_t)l * DD * DD;
        const size_t w1o = (size_t)l * FF * DD;
        const float* bol = bo + (size_t)l * DD;
        const float* b1l = b1 + (size_t)l * FF;
        const float* b2l = b2 + (size_t)l * DD;

        // --- MHA1 (causal) ---
        launch_hgemm(cur_in, wq_h + wqo, wq_l + wqo, nullptr, p_q, MROWS, DD, DD, 0);
        launch_hgemm(cur_in, wk_h + wqo, wk_l + wqo, nullptr, p_k, MROWS, DD, DD, 0);
        launch_hgemm(cur_in, wv_h + wqo, wv_l + wqo, nullptr, p_v, MROWS, DD, DD, 0);
        diag_attn_kernel<<<attn_grid, 256>>>(p_q, p_k, p_v, p_attn, 1);
        launch_hgemm(p_attn, wo_h + wqo, wo_l + wqo, bol, p_a1, MROWS, DD, DD, 0);

        add_ln_kernel<<<MROWS, 256>>>(p_a1, p_xe,
                                      ln1g + (size_t)l * DD, ln1b + (size_t)l * DD, p_qln);

        // --- MHA2 (no mask; K,V from xe) ---
        launch_hgemm(p_qln, wq_h + wqo, wq_l + wqo, nullptr, p_q, MROWS, DD, DD, 0);
        launch_hgemm(p_xe,  wk_h + wqo, wk_l + wqo, nullptr, p_k, MROWS, DD, DD, 0);
        launch_hgemm(p_xe,  wv_h + wqo, wv_l + wqo, nullptr, p_v, MROWS, DD, DD, 0);
        diag_attn_kernel<<<attn_grid, 256>>>(p_q, p_k, p_v, p_attn, 0);
        launch_hgemm(p_attn, wo_h + wqo, wo_l + wqo, bol, p_a2, MROWS, DD, DD, 0);

        // --- FF stack 1 ---
        launch_hgemm(p_a2,  w1_h + w1o, w1_l + w1o, b1l, p_hid, MROWS, FF, DD, 1);
        launch_hgemm(p_hid, w2_h + w1o, w2_l + w1o, b2l, p_ff,  MROWS, DD, FF, 0);
        add_ln_kernel<<<MROWS, 256>>>(p_ff, p_a2,
                                      ln2g + (size_t)l * DD, ln2b + (size_t)l * DD, p_ao);

        // --- FF stack 2 ---
        launch_hgemm(p_ao,  w1_h + w1o, w1_l + w1o, b1l, p_hid, MROWS, FF, DD, 1);
        launch_hgemm(p_hid, w2_h + w1o, w2_l + w1o, b2l, p_ff,  MROWS, DD, FF, 0);
        add_ln_kernel<<<MROWS, 256>>>(p_ff, p_ao,
                                      ln3g + (size_t)l * DD, ln3b + (size_t)l * DD, p_cur);
    }

    // --- Decoder ---
    launch_sgemm(p_cur, Wdec, bdec, (float*)d_out, MROWS, EE, DD, 0);
}

// round 4
// speedup vs baseline: 2.9638x; 1.2358x over previous
#include <cuda_runtime.h>
#include <cuda_fp16.h>
#include <cstdint>
#include <cstddef>

// ---------------------------------------------------------------------------
// Problem constants
// ---------------------------------------------------------------------------
#define BB   32
#define NN   144
#define EE   127
#define DD   512
#define HH   8
#define DK   64
#define DV   64
#define FF   16384
#define LL   4
#define MROWS (BB*NN)        // 4608
#define KENC  (EE+1)         // 513

// ---------------------------------------------------------------------------
// Scratch (static device globals)
// ---------------------------------------------------------------------------
__device__ float g_xp  [MROWS * KENC];
__device__ float g_xe  [MROWS * DD];
__device__ float g_cur [MROWS * DD];
__device__ float g_q   [MROWS * DD];
__device__ float g_qkv [MROWS * 3 * DD];   // fused q|k|v, row stride 1536
__device__ float g_kv  [MROWS * 2 * DD];   // fused k|v,   row stride 1024
__device__ float g_attn[MROWS * DD];
__device__ float g_a1  [MROWS * DD];
__device__ float g_qln [MROWS * DD];
__device__ float g_a2  [MROWS * DD];
__device__ float g_ff  [MROWS * DD];
__device__ float g_ao  [MROWS * DD];
__device__ float g_hid [MROWS * FF];

// Transposed fp16 weights, [Nrows, K] row-major per layer.
// g_wqkvT packs [Wq; Wk; Wv] -> 1536 rows per layer.
__device__ __half g_wqkvT[(size_t)LL * 3 * DD * DD];
__device__ __half g_woT  [(size_t)LL * DD * DD];
__device__ __half g_w1T  [(size_t)LL * FF * DD];
__device__ __half g_w2T  [(size_t)LL * DD * FF];

// ---------------------------------------------------------------------------
// Small helpers
// ---------------------------------------------------------------------------
__device__ __forceinline__ uint32_t smem_u32(const void* p) {
    uint32_t a;
    asm("{ .reg .u64 t; cvta.to.shared.u64 t, %1; cvt.u32.u64 %0, t; }" : "=r"(a) : "l"(p));
    return a;
}
__device__ __forceinline__ uint32_t hpack(__half a, __half b) {
    __half2 t = __halves2half2(a, b);
    return *reinterpret_cast<uint32_t*>(&t);
}
__device__ __forceinline__ void sts16(uint32_t a, uint32_t u0, uint32_t u1,
                                      uint32_t u2, uint32_t u3) {
    asm volatile("st.shared.v4.b32 [%0], {%1, %2, %3, %4};"
                 :: "r"(a), "r"(u0), "r"(u1), "r"(u2), "r"(u3) : "memory");
}
__device__ __forceinline__ void cpa16(uint32_t d, const void* s) {
    asm volatile("cp.async.cg.shared.global [%0], [%1], 16;" :: "r"(d), "l"(s));
}
__device__ __forceinline__ void cpa_commit() {
    asm volatile("cp.async.commit_group;" ::: "memory");
}
__device__ __forceinline__ void ldsm4(uint32_t a, uint32_t& r0, uint32_t& r1,
                                      uint32_t& r2, uint32_t& r3) {
    asm volatile("ldmatrix.sync.aligned.m8n8.x4.shared.b16 {%0,%1,%2,%3}, [%4];"
                 : "=r"(r0), "=r"(r1), "=r"(r2), "=r"(r3) : "r"(a));
}
__device__ __forceinline__ void mma16816(float* c, const uint32_t* a,
                                         uint32_t b0, uint32_t b1) {
    asm volatile("mma.sync.aligned.m16n8k16.row.col.f32.f16.f16.f32 "
                 "{%0,%1,%2,%3},{%4,%5,%6,%7},{%8,%9},{%0,%1,%2,%3};"
                 : "+f"(c[0]), "+f"(c[1]), "+f"(c[2]), "+f"(c[3])
                 : "r"(a[0]), "r"(a[1]), "r"(a[2]), "r"(a[3]), "r"(b0), "r"(b1));
}

// ---------------------------------------------------------------------------
// HMMA 2-pass fp16 GEMM: C[M,N] = A[M,K](fp32) @ fp16(B)[K,N]
// B pre-transposed fp16 [N,K]. A split hi/lo fp16 on the fly:
//   C = (Ah + Al) * Bh  (error = A @ (B - fp16(B)) ~ 1.4e-4 relative)
// Block tile 128x128, BK=32, 256 threads (8 warps: 2M x 4N), warp tile 64x32.
// Requires M%128==0, N%128==0, K%32==0. N is also C's row stride.
// ---------------------------------------------------------------------------
#define SA   40                 // smem row stride (halves): 80B, ldmatrix conflict-free
#define STGB (128 * SA * 2)     // bytes per tile buffer = 10240
#define HMMA_SMEM (6 * STGB)    // AH[2], AL[2], BH[2] = 61440

__global__ void __launch_bounds__(256, 1)
hmma_gemm(const float* __restrict__ A,
          const __half* __restrict__ Bh,
          const float* __restrict__ bias,
          float* __restrict__ C,
          int M, int N, int K, int relu)
{
    extern __shared__ __half smraw[];
    const uint32_t sb = smem_u32(smraw);
    const uint32_t OF_AH = 0, OF_AL = 2 * STGB, OF_BH = 4 * STGB;

    const int tid  = threadIdx.x;
    const int lane = tid & 31;
    const int wid  = tid >> 5;
    const int wm   = wid >> 2;        // 0..1
    const int wn   = wid & 3;         // 0..3
    const int bm   = blockIdx.y * 128;
    const int bn   = blockIdx.x * 128;

    // A staging: thread covers row=tid>>1, 16 cols at (tid&1)*16
    const int arow = tid >> 1;
    const int acol = (tid & 1) * 16;
    const float* Ap = A + (size_t)(bm + arow) * K + acol;
    const uint32_t a_sts = (uint32_t)(arow * SA + acol) * 2;

    // B staging: thread covers row=tid>>1, two 16B segs at seg=(tid&1)*2
    const int brow = tid >> 1;
    const int bseg = (tid & 1) * 2;
    const __half* Bhp = Bh + (size_t)(bn + brow) * K + bseg * 8;
    const uint32_t b_sts = (uint32_t)(brow * SA) * 2 + bseg * 16;

    // ldmatrix lane addressing
    const int r  = lane & 7;
    const int q1 = (lane >> 3) & 1;
    const int q2 = lane >> 4;
    const uint32_t oa = (uint32_t)((wm * 64 + q1 * 8 + r) * SA + q2 * 8) * 2;
    const uint32_t ob = (uint32_t)((wn * 32 + q2 * 8 + r) * SA + q1 * 8) * 2;

    float acc[4][4][4];
#pragma unroll
    for (int i = 0; i < 4; i++)
#pragma unroll
        for (int j = 0; j < 4; j++)
#pragma unroll
            for (int t = 0; t < 4; t++) acc[i][j][t] = 0.f;

    const int niter = K / 32;
    float4 ar[4];

    // ---- prologue ----
    {
        const uint32_t dh = sb + OF_BH + b_sts;
        cpa16(dh,      Bhp);
        cpa16(dh + 16, Bhp + 8);
        cpa_commit();
#pragma unroll
        for (int j = 0; j < 4; j++) ar[j] = *(const float4*)(Ap + j * 4);
    }

    for (int i = 0; i < niter; i++) {
        const int s = i & 1;
        const uint32_t so = (uint32_t)s * STGB;

        // ---- STS A(i): convert fp32 -> fp16 hi/lo ----
        {
            float v[16];
#pragma unroll
            for (int j = 0; j < 4; j++) {
                v[j * 4 + 0] = ar[j].x; v[j * 4 + 1] = ar[j].y;
                v[j * 4 + 2] = ar[j].z; v[j * 4 + 3] = ar[j].w;
            }
            uint32_t hi[8], lo[8];
#pragma unroll
            for (int j = 0; j < 8; j++) {
                float x = v[2 * j], y = v[2 * j + 1];
                __half hx = __float2half_rn(x);
                __half hy = __float2half_rn(y);
                hi[j] = hpack(hx, hy);
                lo[j] = hpack(__float2half_rn(x - __half2float(hx)),
                              __float2half_rn(y - __half2float(hy)));
            }
            const uint32_t dah = sb + OF_AH + so + a_sts;
            const uint32_t dal = sb + OF_AL + so + a_sts;
            sts16(dah,      hi[0], hi[1], hi[2], hi[3]);
            sts16(dah + 16, hi[4], hi[5], hi[6], hi[7]);
            sts16(dal,      lo[0], lo[1], lo[2], lo[3]);
            sts16(dal + 16, lo[4], lo[5], lo[6], lo[7]);
        }

        // ---- issue next-iter loads ----
        if (i + 1 < niter) {
            const uint32_t so1 = (uint32_t)((i + 1) & 1) * STGB;
            const uint32_t dh = sb + OF_BH + so1 + b_sts;
            const __half* bh = Bhp + (size_t)(i + 1) * 32;
            cpa16(dh,      bh);
            cpa16(dh + 16, bh + 8);
            cpa_commit();
            const float* ap = Ap + (size_t)(i + 1) * 32;
#pragma unroll
            for (int j = 0; j < 4; j++) ar[j] = *(const float4*)(ap + j * 4);
            asm volatile("cp.async.wait_group 1;" ::: "memory");
        } else {
            asm volatile("cp.async.wait_group 0;" ::: "memory");
        }
        __syncthreads();

        // ---- compute stage s: 2 k16 steps x 2 passes x 16 mma ----
#pragma unroll
        for (int ks = 0; ks < 2; ks++) {
            const uint32_t ko = (uint32_t)ks * 32;
            uint32_t ah[4][4], al[4][4], bhf[2][4];
#pragma unroll
            for (int mi = 0; mi < 4; mi++) {
                const uint32_t aoff = oa + (uint32_t)(mi * 16 * SA) * 2 + ko;
                ldsm4(sb + OF_AH + so + aoff, ah[mi][0], ah[mi][1], ah[mi][2], ah[mi][3]);
                ldsm4(sb + OF_AL + so + aoff, al[mi][0], al[mi][1], al[mi][2], al[mi][3]);
            }
#pragma unroll
            for (int p = 0; p < 2; p++) {
                const uint32_t boff = ob + (uint32_t)(p * 16 * SA) * 2 + ko;
                ldsm4(sb + OF_BH + so + boff, bhf[p][0], bhf[p][1], bhf[p][2], bhf[p][3]);
            }
#pragma unroll
            for (int mi = 0; mi < 4; mi++)
#pragma unroll
                for (int ni = 0; ni < 4; ni++) {
                    const int p = ni >> 1, e = (ni & 1) * 2;
                    mma16816(acc[mi][ni], ah[mi], bhf[p][e], bhf[p][e + 1]);
                }
#pragma unroll
            for (int mi = 0; mi < 4; mi++)
#pragma unroll
                for (int ni = 0; ni < 4; ni++) {
                    const int p = ni >> 1, e = (ni & 1) * 2;
                    mma16816(acc[mi][ni], al[mi], bhf[p][e], bhf[p][e + 1]);
                }
        }
        __syncthreads();
    }

    // ---- epilogue ----
    const int erow = lane >> 2;
    const int ecol = (lane & 3) * 2;
#pragma unroll
    for (int mi = 0; mi < 4; mi++) {
        const int gr = bm + wm * 64 + mi * 16 + erow;
#pragma unroll
        for (int ni = 0; ni < 4; ni++) {
            const int gc = bn + wn * 32 + ni * 8 + ecol;
            float2 v0 = make_float2(acc[mi][ni][0], acc[mi][ni][1]);
            float2 v1 = make_float2(acc[mi][ni][2], acc[mi][ni][3]);
            if (bias) {
                float bx = bias[gc], by = bias[gc + 1];
                v0.x += bx; v0.y += by; v1.x += bx; v1.y += by;
            }
            if (relu) {
                v0.x = fmaxf(v0.x, 0.f); v0.y = fmaxf(v0.y, 0.f);
                v1.x = fmaxf(v1.x, 0.f); v1.y = fmaxf(v1.y, 0.f);
            }
            *(float2*)(C + (size_t)gr * N + gc)       = v0;
            *(float2*)(C + (size_t)(gr + 8) * N + gc) = v1;
        }
    }
}

// ---------------------------------------------------------------------------
// Weight transpose + fp16 convert: W[K,N] fp32 -> Th [rowOff+n, k] fp16.
// blockIdx.z = layer; separate in/out layer strides for packed outputs.
// ---------------------------------------------------------------------------
__global__ void wconv_kernel(const float* __restrict__ W,
                             __half* __restrict__ Th,
                             int K, int N,
                             size_t inLS, size_t outLS, int rowOff)
{
    __shared__ float t[32][33];
    const float* Wz = W + (size_t)blockIdx.z * inLS;
    __half* Thz = Th + (size_t)blockIdx.z * outLS;
    const int n0 = blockIdx.x * 32, k0 = blockIdx.y * 32;
    const int tx = threadIdx.x, ty = threadIdx.y;
#pragma unroll
    for (int i = 0; i < 32; i += 8)
        t[ty + i][tx] = Wz[(size_t)(k0 + ty + i) * N + n0 + tx];
    __syncthreads();
#pragma unroll
    for (int i = 0; i < 32; i += 8) {
        float f = t[tx][ty + i];
        Thz[(size_t)(rowOff + n0 + ty + i) * K + k0 + tx] = __float2half_rn(f);
    }
}

// ---------------------------------------------------------------------------
// Fallback fp32 SGEMM (encoder K=513, decoder N=127)
// ---------------------------------------------------------------------------
#define BM 128
#define BN 128
#define BK 16

__global__ void __launch_bounds__(256)
sgemm_kernel(const float* __restrict__ A, const float* __restrict__ B,
             const float* __restrict__ bias, float* __restrict__ C,
             int M, int N, int K, int relu)
{
    __shared__ __align__(16) float As[BK][BM];
    __shared__ __align__(16) float Bs[BK][BN];

    const int tid = threadIdx.x;
    const int tx = tid & 15, ty = tid >> 4;
    const int bm = blockIdx.y * BM, bn = blockIdx.x * BN;

    float acc[8][8];
#pragma unroll
    for (int i = 0; i < 8; i++)
#pragma unroll
        for (int j = 0; j < 8; j++) acc[i][j] = 0.f;

    for (int k0 = 0; k0 < K; k0 += BK) {
#pragma unroll
        for (int i = tid; i < BM * BK; i += 256) {
            int m = i >> 4, kk = i & 15;
            int gm = bm + m, gk = k0 + kk;
            As[kk][m] = (gm < M && gk < K) ? A[(size_t)gm * K + gk] : 0.f;
        }
#pragma unroll
        for (int i = tid; i < BK * BN; i += 256) {
            int kk = i >> 7, n = i & 127;
            int gk = k0 + kk, gn = bn + n;
            Bs[kk][n] = (gk < K && gn < N) ? B[(size_t)gk * N + gn] : 0.f;
        }
        __syncthreads();
#pragma unroll
        for (int kk = 0; kk < BK; kk++) {
            float4 a0 = *(const float4*)&As[kk][ty * 4];
            float4 a1 = *(const float4*)&As[kk][ty * 4 + 64];
            float4 b0 = *(const float4*)&Bs[kk][tx * 4];
            float4 b1 = *(const float4*)&Bs[kk][tx * 4 + 64];
            float arr[8] = {a0.x, a0.y, a0.z, a0.w, a1.x, a1.y, a1.z, a1.w};
            float brr[8] = {b0.x, b0.y, b0.z, b0.w, b1.x, b1.y, b1.z, b1.w};
#pragma unroll
            for (int i = 0; i < 8; i++)
#pragma unroll
                for (int j = 0; j < 8; j++)
                    acc[i][j] += arr[i] * brr[j];
        }
        __syncthreads();
    }
#pragma unroll
    for (int i = 0; i < 8; i++) {
        int lm = (i < 4) ? (ty * 4 + i) : (64 + ty * 4 + i - 4);
        int gm = bm + lm;
        if (gm >= M) continue;
#pragma unroll
        for (int j = 0; j < 8; j++) {
            int ln = (j < 4) ? (tx * 4 + j) : (64 + tx * 4 + j - 4);
            int gn = bn + ln;
            if (gn >= N) continue;
            float val = acc[i][j];
            if (bias) val += bias[gn];
            if (relu) val = fmaxf(val, 0.f);
            C[(size_t)gm * N + gn] = val;
        }
    }
}

// ---------------------------------------------------------------------------
// Positional-encoding concat
// ---------------------------------------------------------------------------
__global__ void concat_pe_kernel(const float* __restrict__ x, float* __restrict__ xp)
{
    int idx = blockIdx.x * 256 + threadIdx.x;
    if (idx >= MROWS * KENC) return;
    int row = idx / KENC;
    int c = idx - row * KENC;
    float val;
    if (c < EE) val = x[(size_t)row * EE + c];
    else        val = (float)(row % NN) * (1.f / (float)(NN - 1));
    xp[idx] = val;
}

// ---------------------------------------------------------------------------
// Diagonal-softmax attention with strided q/k/v (for fused qkv buffers).
// out[b,n,h*64+d] = softmax-row-diag * v ; out row stride = DD.
// ---------------------------------------------------------------------------
__global__ void __launch_bounds__(256)
diag_attn_kernel(const float* __restrict__ q, int ldq,
                 const float* __restrict__ k, int ldk,
                 const float* __restrict__ v, int ldv,
                 float* __restrict__ out, int masked)
{
    const int n = blockIdx.x, h = blockIdx.y, b = blockIdx.z;
    const int t = threadIdx.x;

    __shared__ float qs[DK];
    __shared__ float sc[256];
    __shared__ float red[256];

    const int row = b * NN + n;
    const int hoff = h * DK;
    if (t < DK) qs[t] = q[(size_t)row * ldq + hoff + t];
    __syncthreads();

    const int mlim = masked ? (n + 1) : NN;
    float s = 0.f;
    if (t < mlim) {
        const float* kr = k + (size_t)(b * NN + t) * ldk + hoff;
#pragma unroll
        for (int d = 0; d < DK; d++) s += qs[d] * kr[d];
    }
    sc[t] = s;
    red[t] = (t < mlim) ? s : -3.0e38f;
    __syncthreads();
#pragma unroll
    for (int off = 128; off > 0; off >>= 1) {
        if (t < off) red[t] = fmaxf(red[t], red[t + off]);
        __syncthreads();
    }
    const float mx = red[0];
    __syncthreads();
    red[t] = (t < mlim) ? expf(sc[t] - mx) : 0.f;
    __syncthreads();
#pragma unroll
    for (int off = 128; off > 0; off >>= 1) {
        if (t < off) red[t] += red[t + off];
        __syncthreads();
    }
    const float denom = red[0];
    const float dcoef = expf(sc[n] - mx) / denom;

    if (t < DV)
        out[(size_t)row * DD + hoff + t] = dcoef * v[(size_t)row * ldv + hoff + t];
}

// ---------------------------------------------------------------------------
// Fused residual add + LayerNorm (D=512)
// ---------------------------------------------------------------------------
__global__ void __launch_bounds__(256)
add_ln_kernel(const float* __restrict__ a, const float* __restrict__ r,
              const float* __restrict__ g, const float* __restrict__ beta,
              float* __restrict__ out)
{
    const int row = blockIdx.x;
    const int t = threadIdx.x;
    __shared__ float red[256];

    const size_t base = (size_t)row * DD;
    const float x0 = a[base + t] + r[base + t];
    const float x1 = a[base + 256 + t] + r[base + 256 + t];

    red[t] = x0 + x1;
    __syncthreads();
#pragma unroll
    for (int off = 128; off > 0; off >>= 1) {
        if (t < off) red[t] += red[t + off];
        __syncthreads();
    }
    const float mean = red[0] * (1.f / (float)DD);
    __syncthreads();
    const float d0 = x0 - mean, d1 = x1 - mean;
    red[t] = d0 * d0 + d1 * d1;
    __syncthreads();
#pragma unroll
    for (int off = 128; off > 0; off >>= 1) {
        if (t < off) red[t] += red[t + off];
        __syncthreads();
    }
    const float inv = rsqrtf(red[0] * (1.f / (float)DD) + 1e-5f);

    out[base + t]       = d0 * inv * g[t]       + beta[t];
    out[base + 256 + t] = d1 * inv * g[256 + t] + beta[256 + t];
}

// ---------------------------------------------------------------------------
// Host orchestration
// ---------------------------------------------------------------------------
static inline void launch_sgemm(const float* A, const float* B, const float* bias,
                                float* C, int M, int N, int K, int relu)
{
    dim3 grid((N + BN - 1) / BN, (M + BM - 1) / BM);
    sgemm_kernel<<<grid, 256>>>(A, B, bias, C, M, N, K, relu);
}

static inline void launch_hgemm(const float* A, const __half* Bh, const float* bias,
                                float* C, int M, int N, int K, int relu)
{
    dim3 grid(N / 128, M / 128);
    hmma_gemm<<<grid, 256, HMMA_SMEM>>>(A, Bh, bias, C, M, N, K, relu);
}

extern "C" void kernel_launch(void* const* d_in, const int* in_sizes, int n_in,
                              void* d_out, int out_size)
{
    const float* x    = (const float*)d_in[1];
    const float* Wenc = (const float*)d_in[3];
    const float* benc = (const float*)d_in[4];
    const float* Wq   = (const float*)d_in[5];
    const float* Wk   = (const float*)d_in[6];
    const float* Wv   = (const float*)d_in[7];
    const float* Wo   = (const float*)d_in[8];
    const float* bo   = (const float*)d_in[9];
    const float* ln1g = (const float*)d_in[10];
    const float* ln1b = (const float*)d_in[11];
    const float* ln2g = (const float*)d_in[12];
    const float* ln2b = (const float*)d_in[13];
    const float* ln3g = (const float*)d_in[14];
    const float* ln3b = (const float*)d_in[15];
    const float* W1   = (const float*)d_in[16];
    const float* b1   = (const float*)d_in[17];
    const float* W2   = (const float*)d_in[18];
    const float* b2   = (const float*)d_in[19];
    const float* Wdec = (const float*)d_in[20];
    const float* bdec = (const float*)d_in[21];

    float *p_xp, *p_xe, *p_cur, *p_q, *p_qkv, *p_kv, *p_attn, *p_a1, *p_qln,
          *p_a2, *p_ff, *p_ao, *p_hid;
    cudaGetSymbolAddress((void**)&p_xp,   g_xp);
    cudaGetSymbolAddress((void**)&p_xe,   g_xe);
    cudaGetSymbolAddress((void**)&p_cur,  g_cur);
    cudaGetSymbolAddress((void**)&p_q,    g_q);
    cudaGetSymbolAddress((void**)&p_qkv,  g_qkv);
    cudaGetSymbolAddress((void**)&p_kv,   g_kv);
    cudaGetSymbolAddress((void**)&p_attn, g_attn);
    cudaGetSymbolAddress((void**)&p_a1,   g_a1);
    cudaGetSymbolAddress((void**)&p_qln,  g_qln);
    cudaGetSymbolAddress((void**)&p_a2,   g_a2);
    cudaGetSymbolAddress((void**)&p_ff,   g_ff);
    cudaGetSymbolAddress((void**)&p_ao,   g_ao);
    cudaGetSymbolAddress((void**)&p_hid,  g_hid);

    __half *wqkv, *wo, *w1, *w2;
    cudaGetSymbolAddress((void**)&wqkv, g_wqkvT);
    cudaGetSymbolAddress((void**)&wo,   g_woT);
    cudaGetSymbolAddress((void**)&w1,   g_w1T);
    cudaGetSymbolAddress((void**)&w2,   g_w2T);

    cudaFuncSetAttribute(hmma_gemm, cudaFuncAttributeMaxDynamicSharedMemorySize, HMMA_SMEM);

    // --- Weight transpose + fp16 convert ---
    {
        dim3 wb(32, 8);
        const size_t dd2 = (size_t)DD * DD;
        // Pack [Wq;Wk;Wv] into wqkv (1536 rows/layer)
        wconv_kernel<<<dim3(DD/32, DD/32, LL), wb>>>(Wq, wqkv, DD, DD, dd2, 3*dd2, 0);
        wconv_kernel<<<dim3(DD/32, DD/32, LL), wb>>>(Wk, wqkv, DD, DD, dd2, 3*dd2, DD);
        wconv_kernel<<<dim3(DD/32, DD/32, LL), wb>>>(Wv, wqkv, DD, DD, dd2, 3*dd2, 2*DD);
        wconv_kernel<<<dim3(DD/32, DD/32, LL), wb>>>(Wo, wo, DD, DD, dd2, dd2, 0);
        const size_t df = (size_t)DD * FF;
        wconv_kernel<<<dim3(FF/32, DD/32, LL), wb>>>(W1, w1, DD, FF, df, df, 0);
        wconv_kernel<<<dim3(DD/32, FF/32, LL), wb>>>(W2, w2, FF, DD, df, df, 0);
    }

    // --- Encoder ---
    {
        int tot = MROWS * KENC;
        concat_pe_kernel<<<(tot + 255) / 256, 256>>>(x, p_xp);
        launch_sgemm(p_xp, Wenc, benc, p_xe, MROWS, DD, KENC, 0);
    }

    dim3 attn_grid(NN, HH, BB);

    for (int l = 0; l < LL; l++) {
        const float* cur_in = (l == 0) ? p_xe : p_cur;
        const __half* wqkv_l = wqkv + (size_t)l * 3 * DD * DD;
        const __half* wkv_l  = wqkv_l + (size_t)DD * DD;     // rows 512..1535
        const __half* wo_l   = wo + (size_t)l * DD * DD;
        const __half* w1_l   = w1 + (size_t)l * DD * FF;
        const __half* w2_l   = w2 + (size_t)l * DD * FF;
        const float* bol = bo + (size_t)l * DD;
        const float* b1l = b1 + (size_t)l * FF;
        const float* b2l = b2 + (size_t)l * DD;

        // --- MHA1 (causal): fused QKV projection ---
        launch_hgemm(cur_in, wqkv_l, nullptr, p_qkv, MROWS, 3 * DD, DD, 0);
        diag_attn_kernel<<<attn_grid, 256>>>(p_qkv, 3 * DD,
                                             p_qkv + DD, 3 * DD,
                                             p_qkv + 2 * DD, 3 * DD, p_attn, 1);
        launch_hgemm(p_attn, wo_l, bol, p_a1, MROWS, DD, DD, 0);

        add_ln_kernel<<<MROWS, 256>>>(p_a1, p_xe,
                                      ln1g + (size_t)l * DD, ln1b + (size_t)l * DD, p_qln);

        // --- MHA2 (no mask; K,V from xe): Q separate, KV fused ---
        launch_hgemm(p_qln, wqkv_l, nullptr, p_q, MROWS, DD, DD, 0);
        launch_hgemm(p_xe,  wkv_l,  nullptr, p_kv, MROWS, 2 * DD, DD, 0);
        diag_attn_kernel<<<attn_grid, 256>>>(p_q, DD,
                                             p_kv, 2 * DD,
                                             p_kv + DD, 2 * DD, p_attn, 0);
        launch_hgemm(p_attn, wo_l, bol, p_a2, MROWS, DD, DD, 0);

        // --- FF stack 1 ---
        launch_hgemm(p_a2,  w1_l, b1l, p_hid, MROWS, FF, DD, 1);
        launch_hgemm(p_hid, w2_l, b2l, p_ff,  MROWS, DD, FF, 0);
        add_ln_kernel<<<MROWS, 256>>>(p_ff, p_a2,
                                      ln2g + (size_t)l * DD, ln2b + (size_t)l * DD, p_ao);

        // --- FF stack 2 ---
        launch_hgemm(p_ao,  w1_l, b1l, p_hid, MROWS, FF, DD, 1);
        launch_hgemm(p_hid, w2_l, b2l, p_ff,  MROWS, DD, FF, 0);
        add_ln_kernel<<<MROWS, 256>>>(p_ff, p_ao,
                                      ln3g + (size_t)l * DD, ln3b + (size_t)l * DD, p_cur);
    }

    // --- Decoder ---
    launch_sgemm(p_cur, Wdec, bdec, (float*)d_out, MROWS, EE, DD, 0);
}

// round 5
// speedup vs baseline: 3.2826x; 1.1076x over previous
#include <cuda_runtime.h>
#include <cuda_fp16.h>
#include <cstdint>
#include <cstddef>

// ---------------------------------------------------------------------------
// Problem constants
// ---------------------------------------------------------------------------
#define BB   32
#define NN   144
#define EE   127
#define DD   512
#define HH   8
#define DK   64
#define DV   64
#define FF   16384
#define LL   4
#define MROWS (BB*NN)        // 4608
#define KENC  (EE+1)         // 513

// ---------------------------------------------------------------------------
// Scratch (static device globals)
// ---------------------------------------------------------------------------
__device__ float g_xp  [MROWS * KENC];
__device__ float g_xe  [MROWS * DD];
__device__ float g_cur [MROWS * DD];
__device__ float g_q   [MROWS * DD];
__device__ float g_qkv [MROWS * 3 * DD];
__device__ float g_kv  [MROWS * 2 * DD];
__device__ float g_a1  [MROWS * DD];
__device__ float g_a2  [MROWS * DD];
__device__ float g_ff  [MROWS * DD];
__device__ float g_ao  [MROWS * DD];

// fp16 hi/lo split activations
__device__ __half g_xe_h [MROWS * DD], g_xe_l [MROWS * DD];
__device__ __half g_cur_h[MROWS * DD], g_cur_l[MROWS * DD];
__device__ __half g_qln_h[MROWS * DD], g_qln_l[MROWS * DD];
__device__ __half g_a2_h [MROWS * DD], g_a2_l [MROWS * DD];
__device__ __half g_ao_h [MROWS * DD], g_ao_l [MROWS * DD];
__device__ __half g_at_h [MROWS * DD], g_at_l [MROWS * DD];
__device__ __half g_hid_h[(size_t)MROWS * FF], g_hid_l[(size_t)MROWS * FF];

// Transposed fp16 weights, [Nrows, K] row-major per layer.
__device__ __half g_wqkvT[(size_t)LL * 3 * DD * DD];
__device__ __half g_woT  [(size_t)LL * DD * DD];
__device__ __half g_w1T  [(size_t)LL * FF * DD];
__device__ __half g_w2T  [(size_t)LL * DD * FF];

// ---------------------------------------------------------------------------
// Small helpers
// ---------------------------------------------------------------------------
__device__ __forceinline__ uint32_t smem_u32(const void* p) {
    uint32_t a;
    asm("{ .reg .u64 t; cvta.to.shared.u64 t, %1; cvt.u32.u64 %0, t; }" : "=r"(a) : "l"(p));
    return a;
}
__device__ __forceinline__ void cpa16(uint32_t d, const void* s) {
    asm volatile("cp.async.cg.shared.global [%0], [%1], 16;" :: "r"(d), "l"(s));
}
__device__ __forceinline__ void cpa_commit() {
    asm volatile("cp.async.commit_group;" ::: "memory");
}
__device__ __forceinline__ void ldsm4(uint32_t a, uint32_t& r0, uint32_t& r1,
                                      uint32_t& r2, uint32_t& r3) {
    asm volatile("ldmatrix.sync.aligned.m8n8.x4.shared.b16 {%0,%1,%2,%3}, [%4];"
                 : "=r"(r0), "=r"(r1), "=r"(r2), "=r"(r3) : "r"(a));
}
__device__ __forceinline__ void mma16816(float* c, const uint32_t* a,
                                         uint32_t b0, uint32_t b1) {
    asm volatile("mma.sync.aligned.m16n8k16.row.col.f32.f16.f16.f32 "
                 "{%0,%1,%2,%3},{%4,%5,%6,%7},{%8,%9},{%0,%1,%2,%3};"
                 : "+f"(c[0]), "+f"(c[1]), "+f"(c[2]), "+f"(c[3])
                 : "r"(a[0]), "r"(a[1]), "r"(a[2]), "r"(a[3]), "r"(b0), "r"(b1));
}
__device__ __forceinline__ void split2(float x, float y, __half2& h, __half2& l) {
    __half hx = __float2half_rn(x);
    __half hy = __float2half_rn(y);
    h = __halves2half2(hx, hy);
    l = __halves2half2(__float2half_rn(x - __half2float(hx)),
                       __float2half_rn(y - __half2float(hy)));
}

// ---------------------------------------------------------------------------
// HMMA 2-pass fp16 GEMM: C = (Ah + Al) @ Bh^T(stored [N,K])
// All operands fp16 in gmem. 128x128x32 tile, 3-stage cp.async pipeline,
// 256 threads (8 warps: 2M x 4N), warp tile 64x32.
// Outputs: optional fp32 C (ldc=N), optional fp16 hi/lo split Ch/Cl.
// Requires M%128==0, N%128==0, K%32==0.
// ---------------------------------------------------------------------------
#define SA    40                    // smem row stride (halves) -> conflict-free ldmatrix
#define TILEB (128 * SA * 2)        // 10240 bytes per tile
#define STAGEB (3 * TILEB)          // Ah, Al, Bh per stage
#define HMMA_SMEM (3 * STAGEB)      // 92160 bytes

__global__ void __launch_bounds__(256)
hmma_gemm(const __half* __restrict__ Ah, const __half* __restrict__ Al,
          const __half* __restrict__ Bh,
          const float* __restrict__ bias,
          float* __restrict__ C,
          __half* __restrict__ Ch, __half* __restrict__ Cl,
          int M, int N, int K, int relu)
{
    extern __shared__ __half smraw[];
    const uint32_t sb = smem_u32(smraw);

    const int tid  = threadIdx.x;
    const int lane = tid & 31;
    const int wid  = tid >> 5;
    const int wm   = wid >> 2;
    const int wn   = wid & 3;
    const int bm   = blockIdx.y * 128;
    const int bn   = blockIdx.x * 128;

    // staging: thread covers tile row = tid>>1, 16 halves at col (tid&1)*16
    const int srow = tid >> 1;
    const int scol = (tid & 1) * 16;
    const __half* Ahp = Ah + (size_t)(bm + srow) * K + scol;
    const __half* Alp = Al + (size_t)(bm + srow) * K + scol;
    const __half* Bhp = Bh + (size_t)(bn + srow) * K + scol;
    const uint32_t sts = (uint32_t)(srow * SA + scol) * 2;

    // ldmatrix lane addressing
    const int r  = lane & 7;
    const int q1 = (lane >> 3) & 1;
    const int q2 = lane >> 4;
    const uint32_t oa = (uint32_t)((wm * 64 + q1 * 8 + r) * SA + q2 * 8) * 2;
    const uint32_t ob = (uint32_t)((wn * 32 + q2 * 8 + r) * SA + q1 * 8) * 2;

    float acc[4][4][4];
#pragma unroll
    for (int i = 0; i < 4; i++)
#pragma unroll
        for (int j = 0; j < 4; j++)
#pragma unroll
            for (int t = 0; t < 4; t++) acc[i][j][t] = 0.f;

    const int niter = K / 32;

    // stage loader
    auto load_stage = [&](int j) {
        const uint32_t so = (uint32_t)(j % 3) * STAGEB;
        const size_t ko = (size_t)j * 32;
        cpa16(sb + so + sts,                  Ahp + ko);
        cpa16(sb + so + sts + 16,             Ahp + ko + 8);
        cpa16(sb + so + TILEB + sts,          Alp + ko);
        cpa16(sb + so + TILEB + sts + 16,     Alp + ko + 8);
        cpa16(sb + so + 2 * TILEB + sts,      Bhp + ko);
        cpa16(sb + so + 2 * TILEB + sts + 16, Bhp + ko + 8);
        cpa_commit();
    };

    load_stage(0);
    if (niter > 1) load_stage(1);

    for (int i = 0; i < niter; i++) {
        if (i + 1 < niter) asm volatile("cp.async.wait_group 1;" ::: "memory");
        else               asm volatile("cp.async.wait_group 0;" ::: "memory");
        __syncthreads();

        const uint32_t so = (uint32_t)(i % 3) * STAGEB;
#pragma unroll
        for (int ks = 0; ks < 2; ks++) {
            const uint32_t ko = (uint32_t)ks * 32;
            uint32_t ah[4][4], al[4][4], bhf[2][4];
#pragma unroll
            for (int mi = 0; mi < 4; mi++) {
                const uint32_t aoff = oa + (uint32_t)(mi * 16 * SA) * 2 + ko;
                ldsm4(sb + so + aoff,          ah[mi][0], ah[mi][1], ah[mi][2], ah[mi][3]);
                ldsm4(sb + so + TILEB + aoff,  al[mi][0], al[mi][1], al[mi][2], al[mi][3]);
            }
#pragma unroll
            for (int p = 0; p < 2; p++) {
                const uint32_t boff = ob + (uint32_t)(p * 16 * SA) * 2 + ko;
                ldsm4(sb + so + 2 * TILEB + boff, bhf[p][0], bhf[p][1], bhf[p][2], bhf[p][3]);
            }
#pragma unroll
            for (int mi = 0; mi < 4; mi++)
#pragma unroll
                for (int ni = 0; ni < 4; ni++) {
                    const int p = ni >> 1, e = (ni & 1) * 2;
                    mma16816(acc[mi][ni], ah[mi], bhf[p][e], bhf[p][e + 1]);
                }
#pragma unroll
            for (int mi = 0; mi < 4; mi++)
#pragma unroll
                for (int ni = 0; ni < 4; ni++) {
                    const int p = ni >> 1, e = (ni & 1) * 2;
                    mma16816(acc[mi][ni], al[mi], bhf[p][e], bhf[p][e + 1]);
                }
        }
        if (i + 2 < niter) load_stage(i + 2);
    }

    // ---- epilogue ----
    const int erow = lane >> 2;
    const int ecol = (lane & 3) * 2;
#pragma unroll
    for (int mi = 0; mi < 4; mi++) {
        const int gr = bm + wm * 64 + mi * 16 + erow;
#pragma unroll
        for (int ni = 0; ni < 4; ni++) {
            const int gc = bn + wn * 32 + ni * 8 + ecol;
            float2 v0 = make_float2(acc[mi][ni][0], acc[mi][ni][1]);
            float2 v1 = make_float2(acc[mi][ni][2], acc[mi][ni][3]);
            if (bias) {
                float bx = bias[gc], by = bias[gc + 1];
                v0.x += bx; v0.y += by; v1.x += bx; v1.y += by;
            }
            if (relu) {
                v0.x = fmaxf(v0.x, 0.f); v0.y = fmaxf(v0.y, 0.f);
                v1.x = fmaxf(v1.x, 0.f); v1.y = fmaxf(v1.y, 0.f);
            }
            const size_t o0 = (size_t)gr * N + gc;
            const size_t o1 = (size_t)(gr + 8) * N + gc;
            if (C) {
                *(float2*)(C + o0) = v0;
                *(float2*)(C + o1) = v1;
            }
            if (Ch) {
                __half2 h0, l0, h1, l1;
                split2(v0.x, v0.y, h0, l0);
                split2(v1.x, v1.y, h1, l1);
                *(__half2*)(Ch + o0) = h0; *(__half2*)(Cl + o0) = l0;
                *(__half2*)(Ch + o1) = h1; *(__half2*)(Cl + o1) = l1;
            }
        }
    }
}

// ---------------------------------------------------------------------------
// Weight transpose + fp16 convert: W[K,N] fp32 -> Th [rowOff+n, k] fp16.
// ---------------------------------------------------------------------------
__global__ void wconv_kernel(const float* __restrict__ W,
                             __half* __restrict__ Th,
                             int K, int N,
                             size_t inLS, size_t outLS, int rowOff)
{
    __shared__ float t[32][33];
    const float* Wz = W + (size_t)blockIdx.z * inLS;
    __half* Thz = Th + (size_t)blockIdx.z * outLS;
    const int n0 = blockIdx.x * 32, k0 = blockIdx.y * 32;
    const int tx = threadIdx.x, ty = threadIdx.y;
#pragma unroll
    for (int i = 0; i < 32; i += 8)
        t[ty + i][tx] = Wz[(size_t)(k0 + ty + i) * N + n0 + tx];
    __syncthreads();
#pragma unroll
    for (int i = 0; i < 32; i += 8) {
        float f = t[tx][ty + i];
        Thz[(size_t)(rowOff + n0 + ty + i) * K + k0 + tx] = __float2half_rn(f);
    }
}

// ---------------------------------------------------------------------------
// Elementwise fp32 -> fp16 hi/lo split
// ---------------------------------------------------------------------------
__global__ void split_kernel(const float* __restrict__ x,
                             __half* __restrict__ h, __half* __restrict__ l, int n)
{
    int i = (blockIdx.x * 256 + threadIdx.x) * 4;
    if (i >= n) return;
    float4 f = *(const float4*)(x + i);
    __half2 h0, l0, h1, l1;
    split2(f.x, f.y, h0, l0);
    split2(f.z, f.w, h1, l1);
    *(__half2*)(h + i)     = h0;
    *(__half2*)(h + i + 2) = h1;
    *(__half2*)(l + i)     = l0;
    *(__half2*)(l + i + 2) = l1;
}

// ---------------------------------------------------------------------------
// Fallback fp32 SGEMM (encoder K=513, decoder N=127)
// ---------------------------------------------------------------------------
#define BM 128
#define BN 128
#define BK 16

__global__ void __launch_bounds__(256)
sgemm_kernel(const float* __restrict__ A, const float* __restrict__ B,
             const float* __restrict__ bias, float* __restrict__ C,
             int M, int N, int K, int relu)
{
    __shared__ __align__(16) float As[BK][BM];
    __shared__ __align__(16) float Bs[BK][BN];

    const int tid = threadIdx.x;
    const int tx = tid & 15, ty = tid >> 4;
    const int bm = blockIdx.y * BM, bn = blockIdx.x * BN;

    float acc[8][8];
#pragma unroll
    for (int i = 0; i < 8; i++)
#pragma unroll
        for (int j = 0; j < 8; j++) acc[i][j] = 0.f;

    for (int k0 = 0; k0 < K; k0 += BK) {
#pragma unroll
        for (int i = tid; i < BM * BK; i += 256) {
            int m = i >> 4, kk = i & 15;
            int gm = bm + m, gk = k0 + kk;
            As[kk][m] = (gm < M && gk < K) ? A[(size_t)gm * K + gk] : 0.f;
        }
#pragma unroll
        for (int i = tid; i < BK * BN; i += 256) {
            int kk = i >> 7, n = i & 127;
            int gk = k0 + kk, gn = bn + n;
            Bs[kk][n] = (gk < K && gn < N) ? B[(size_t)gk * N + gn] : 0.f;
        }
        __syncthreads();
#pragma unroll
        for (int kk = 0; kk < BK; kk++) {
            float4 a0 = *(const float4*)&As[kk][ty * 4];
            float4 a1 = *(const float4*)&As[kk][ty * 4 + 64];
            float4 b0 = *(const float4*)&Bs[kk][tx * 4];
            float4 b1 = *(const float4*)&Bs[kk][tx * 4 + 64];
            float arr[8] = {a0.x, a0.y, a0.z, a0.w, a1.x, a1.y, a1.z, a1.w};
            float brr[8] = {b0.x, b0.y, b0.z, b0.w, b1.x, b1.y, b1.z, b1.w};
#pragma unroll
            for (int i = 0; i < 8; i++)
#pragma unroll
                for (int j = 0; j < 8; j++)
                    acc[i][j] += arr[i] * brr[j];
        }
        __syncthreads();
    }
#pragma unroll
    for (int i = 0; i < 8; i++) {
        int lm = (i < 4) ? (ty * 4 + i) : (64 + ty * 4 + i - 4);
        int gm = bm + lm;
        if (gm >= M) continue;
#pragma unroll
        for (int j = 0; j < 8; j++) {
            int ln = (j < 4) ? (tx * 4 + j) : (64 + tx * 4 + j - 4);
            int gn = bn + ln;
            if (gn >= N) continue;
            float val = acc[i][j];
            if (bias) val += bias[gn];
            if (relu) val = fmaxf(val, 0.f);
            C[(size_t)gm * N + gn] = val;
        }
    }
}

// ---------------------------------------------------------------------------
// Positional-encoding concat
// ---------------------------------------------------------------------------
__global__ void concat_pe_kernel(const float* __restrict__ x, float* __restrict__ xp)
{
    int idx = blockIdx.x * 256 + threadIdx.x;
    if (idx >= MROWS * KENC) return;
    int row = idx / KENC;
    int c = idx - row * KENC;
    float val;
    if (c < EE) val = x[(size_t)row * EE + c];
    else        val = (float)(row % NN) * (1.f / (float)(NN - 1));
    xp[idx] = val;
}

// ---------------------------------------------------------------------------
// Diagonal-softmax attention; emits fp16 hi/lo split output (row stride DD).
// ---------------------------------------------------------------------------
__global__ void __launch_bounds__(256)
diag_attn_kernel(const float* __restrict__ q, int ldq,
                 const float* __restrict__ k, int ldk,
                 const float* __restrict__ v, int ldv,
                 __half* __restrict__ oh, __half* __restrict__ ol, int masked)
{
    const int n = blockIdx.x, h = blockIdx.y, b = blockIdx.z;
    const int t = threadIdx.x;

    __shared__ float qs[DK];
    __shared__ float sc[256];
    __shared__ float red[256];

    const int row = b * NN + n;
    const int hoff = h * DK;
    if (t < DK) qs[t] = q[(size_t)row * ldq + hoff + t];
    __syncthreads();

    const int mlim = masked ? (n + 1) : NN;
    float s = 0.f;
    if (t < mlim) {
        const float* kr = k + (size_t)(b * NN + t) * ldk + hoff;
#pragma unroll
        for (int d = 0; d < DK; d++) s += qs[d] * kr[d];
    }
    sc[t] = s;
    red[t] = (t < mlim) ? s : -3.0e38f;
    __syncthreads();
#pragma unroll
    for (int off = 128; off > 0; off >>= 1) {
        if (t < off) red[t] = fmaxf(red[t], red[t + off]);
        __syncthreads();
    }
    const float mx = red[0];
    __syncthreads();
    red[t] = (t < mlim) ? expf(sc[t] - mx) : 0.f;
    __syncthreads();
#pragma unroll
    for (int off = 128; off > 0; off >>= 1) {
        if (t < off) red[t] += red[t + off];
        __syncthreads();
    }
    const float denom = red[0];
    const float dcoef = expf(sc[n] - mx) / denom;

    if (t < DV) {
        const float val = dcoef * v[(size_t)row * ldv + hoff + t];
        __half hx = __float2half_rn(val);
        oh[(size_t)row * DD + hoff + t] = hx;
        ol[(size_t)row * DD + hoff + t] = __float2half_rn(val - __half2float(hx));
    }
}

// ---------------------------------------------------------------------------
// Fused residual add + LayerNorm (D=512); fp32 out + optional fp16 split out.
// ---------------------------------------------------------------------------
__global__ void __launch_bounds__(256)
add_ln_kernel(const float* __restrict__ a, const float* __restrict__ r,
              const float* __restrict__ g, const float* __restrict__ beta,
              float* __restrict__ out,
              __half* __restrict__ oh, __half* __restrict__ ol)
{
    const int row = blockIdx.x;
    const int t = threadIdx.x;
    __shared__ float red[256];

    const size_t base = (size_t)row * DD;
    const float x0 = a[base + t] + r[base + t];
    const float x1 = a[base + 256 + t] + r[base + 256 + t];

    red[t] = x0 + x1;
    __syncthreads();
#pragma unroll
    for (int off = 128; off > 0; off >>= 1) {
        if (t < off) red[t] += red[t + off];
        __syncthreads();
    }
    const float mean = red[0] * (1.f / (float)DD);
    __syncthreads();
    const float d0 = x0 - mean, d1 = x1 - mean;
    red[t] = d0 * d0 + d1 * d1;
    __syncthreads();
#pragma unroll
    for (int off = 128; off > 0; off >>= 1) {
        if (t < off) red[t] += red[t + off];
        __syncthreads();
    }
    const float inv = rsqrtf(red[0] * (1.f / (float)DD) + 1e-5f);

    const float y0 = d0 * inv * g[t]       + beta[t];
    const float y1 = d1 * inv * g[256 + t] + beta[256 + t];
    out[base + t]       = y0;
    out[base + 256 + t] = y1;
    if (oh) {
        __half h0 = __float2half_rn(y0);
        __half h1 = __float2half_rn(y1);
        oh[base + t]       = h0;
        oh[base + 256 + t] = h1;
        ol[base + t]       = __float2half_rn(y0 - __half2float(h0));
        ol[base + 256 + t] = __float2half_rn(y1 - __half2float(h1));
    }
}

// ---------------------------------------------------------------------------
// Host orchestration
// ---------------------------------------------------------------------------
static inline void launch_sgemm(const float* A, const float* B, const float* bias,
                                float* C, int M, int N, int K, int relu)
{
    dim3 grid((N + BN - 1) / BN, (M + BM - 1) / BM);
    sgemm_kernel<<<grid, 256>>>(A, B, bias, C, M, N, K, relu);
}

static inline void launch_hgemm(const __half* Ah, const __half* Al, const __half* Bh,
                                const float* bias, float* C, __half* Ch, __half* Cl,
                                int M, int N, int K, int relu)
{
    dim3 grid(N / 128, M / 128);
    hmma_gemm<<<grid, 256, HMMA_SMEM>>>(Ah, Al, Bh, bias, C, Ch, Cl, M, N, K, relu);
}

extern "C" void kernel_launch(void* const* d_in, const int* in_sizes, int n_in,
                              void* d_out, int out_size)
{
    const float* x    = (const float*)d_in[1];
    const float* Wenc = (const float*)d_in[3];
    const float* benc = (const float*)d_in[4];
    const float* Wq   = (const float*)d_in[5];
    const float* Wk   = (const float*)d_in[6];
    const float* Wv   = (const float*)d_in[7];
    const float* Wo   = (const float*)d_in[8];
    const float* bo   = (const float*)d_in[9];
    const float* ln1g = (const float*)d_in[10];
    const float* ln1b = (const float*)d_in[11];
    const float* ln2g = (const float*)d_in[12];
    const float* ln2b = (const float*)d_in[13];
    const float* ln3g = (const float*)d_in[14];
    const float* ln3b = (const float*)d_in[15];
    const float* W1   = (const float*)d_in[16];
    const float* b1   = (const float*)d_in[17];
    const float* W2   = (const float*)d_in[18];
    const float* b2   = (const float*)d_in[19];
    const float* Wdec = (const float*)d_in[20];
    const float* bdec = (const float*)d_in[21];

    float *p_xp, *p_xe, *p_cur, *p_q, *p_qkv, *p_kv, *p_a1, *p_a2, *p_ff, *p_ao;
    cudaGetSymbolAddress((void**)&p_xp,  g_xp);
    cudaGetSymbolAddress((void**)&p_xe,  g_xe);
    cudaGetSymbolAddress((void**)&p_cur, g_cur);
    cudaGetSymbolAddress((void**)&p_q,   g_q);
    cudaGetSymbolAddress((void**)&p_qkv, g_qkv);
    cudaGetSymbolAddress((void**)&p_kv,  g_kv);
    cudaGetSymbolAddress((void**)&p_a1,  g_a1);
    cudaGetSymbolAddress((void**)&p_a2,  g_a2);
    cudaGetSymbolAddress((void**)&p_ff,  g_ff);
    cudaGetSymbolAddress((void**)&p_ao,  g_ao);

    __half *xe_h, *xe_l, *cur_h, *cur_l, *qln_h, *qln_l, *a2_h, *a2_l,
           *ao_h, *ao_l, *at_h, *at_l, *hid_h, *hid_l;
    cudaGetSymbolAddress((void**)&xe_h,  g_xe_h);
    cudaGetSymbolAddress((void**)&xe_l,  g_xe_l);
    cudaGetSymbolAddress((void**)&cur_h, g_cur_h);
    cudaGetSymbolAddress((void**)&cur_l, g_cur_l);
    cudaGetSymbolAddress((void**)&qln_h, g_qln_h);
    cudaGetSymbolAddress((void**)&qln_l, g_qln_l);
    cudaGetSymbolAddress((void**)&a2_h,  g_a2_h);
    cudaGetSymbolAddress((void**)&a2_l,  g_a2_l);
    cudaGetSymbolAddress((void**)&ao_h,  g_ao_h);
    cudaGetSymbolAddress((void**)&ao_l,  g_ao_l);
    cudaGetSymbolAddress((void**)&at_h,  g_at_h);
    cudaGetSymbolAddress((void**)&at_l,  g_at_l);
    cudaGetSymbolAddress((void**)&hid_h, g_hid_h);
    cudaGetSymbolAddress((void**)&hid_l, g_hid_l);

    __half *wqkv, *wo, *w1, *w2;
    cudaGetSymbolAddress((void**)&wqkv, g_wqkvT);
    cudaGetSymbolAddress((void**)&wo,   g_woT);
    cudaGetSymbolAddress((void**)&w1,   g_w1T);
    cudaGetSymbolAddress((void**)&w2,   g_w2T);

    cudaFuncSetAttribute(hmma_gemm, cudaFuncAttributeMaxDynamicSharedMemorySize, HMMA_SMEM);

    // --- Weight transpose + fp16 convert ---
    {
        dim3 wb(32, 8);
        const size_t dd2 = (size_t)DD * DD;
        wconv_kernel<<<dim3(DD/32, DD/32, LL), wb>>>(Wq, wqkv, DD, DD, dd2, 3*dd2, 0);
        wconv_kernel<<<dim3(DD/32, DD/32, LL), wb>>>(Wk, wqkv, DD, DD, dd2, 3*dd2, DD);
        wconv_kernel<<<dim3(DD/32, DD/32, LL), wb>>>(Wv, wqkv, DD, DD, dd2, 3*dd2, 2*DD);
        wconv_kernel<<<dim3(DD/32, DD/32, LL), wb>>>(Wo, wo, DD, DD, dd2, dd2, 0);
        const size_t df = (size_t)DD * FF;
        wconv_kernel<<<dim3(FF/32, DD/32, LL), wb>>>(W1, w1, DD, FF, df, df, 0);
        wconv_kernel<<<dim3(DD/32, FF/32, LL), wb>>>(W2, w2, FF, DD, df, df, 0);
    }

    // --- Encoder + split ---
    {
        int tot = MROWS * KENC;
        concat_pe_kernel<<<(tot + 255) / 256, 256>>>(x, p_xp);
        launch_sgemm(p_xp, Wenc, benc, p_xe, MROWS, DD, KENC, 0);
        int n = MROWS * DD;
        split_kernel<<<(n / 4 + 255) / 256, 256>>>(p_xe, xe_h, xe_l, n);
    }

    dim3 attn_grid(NN, HH, BB);
    const int nact = MROWS * DD;

    for (int l = 0; l < LL; l++) {
        const __half* in_h = (l == 0) ? xe_h : cur_h;
        const __half* in_l = (l == 0) ? xe_l : cur_l;
        const __half* wqkv_l = wqkv + (size_t)l * 3 * DD * DD;
        const __half* wkv_l  = wqkv_l + (size_t)DD * DD;
        const __half* wo_l   = wo + (size_t)l * DD * DD;
        const __half* w1_l   = w1 + (size_t)l * DD * FF;
        const __half* w2_l   = w2 + (size_t)l * DD * FF;
        const float* bol = bo + (size_t)l * DD;
        const float* b1l = b1 + (size_t)l * FF;
        const float* b2l = b2 + (size_t)l * DD;

        // --- MHA1 (causal): fused QKV projection ---
        launch_hgemm(in_h, in_l, wqkv_l, nullptr, p_qkv, nullptr, nullptr,
                     MROWS, 3 * DD, DD, 0);
        diag_attn_kernel<<<attn_grid, 256>>>(p_qkv, 3 * DD,
                                             p_qkv + DD, 3 * DD,
                                             p_qkv + 2 * DD, 3 * DD, at_h, at_l, 1);
        launch_hgemm(at_h, at_l, wo_l, bol, p_a1, nullptr, nullptr, MROWS, DD, DD, 0);

        add_ln_kernel<<<MROWS, 256>>>(p_a1, p_xe,
                                      ln1g + (size_t)l * DD, ln1b + (size_t)l * DD,
                                      p_q /*unused fp32 dst*/, qln_h, qln_l);

        // --- MHA2 (no mask): Q from qln, K/V from xe ---
        launch_hgemm(qln_h, qln_l, wqkv_l, nullptr, p_q, nullptr, nullptr,
                     MROWS, DD, DD, 0);
        launch_hgemm(xe_h, xe_l, wkv_l, nullptr, p_kv, nullptr, nullptr,
                     MROWS, 2 * DD, DD, 0);
        diag_attn_kernel<<<attn_grid, 256>>>(p_q, DD,
                                             p_kv, 2 * DD,
                                             p_kv + DD, 2 * DD, at_h, at_l, 0);
        launch_hgemm(at_h, at_l, wo_l, bol, p_a2, a2_h, a2_l, MROWS, DD, DD, 0);

        // --- FF stack 1 ---
        launch_hgemm(a2_h, a2_l, w1_l, b1l, nullptr, hid_h, hid_l, MROWS, FF, DD, 1);
        launch_hgemm(hid_h, hid_l, w2_l, b2l, p_ff, nullptr, nullptr, MROWS, DD, FF, 0);
        add_ln_kernel<<<MROWS, 256>>>(p_ff, p_a2,
                                      ln2g + (size_t)l * DD, ln2b + (size_t)l * DD,
                                      p_ao, ao_h, ao_l);

        // --- FF stack 2 ---
        launch_hgemm(ao_h, ao_l, w1_l, b1l, nullptr, hid_h, hid_l, MROWS, FF, DD, 1);
        launch_hgemm(hid_h, hid_l, w2_l, b2l, p_ff, nullptr, nullptr, MROWS, DD, FF, 0);
        add_ln_kernel<<<MROWS, 256>>>(p_ff, p_ao,
                                      ln3g + (size_t)l * DD, ln3b + (size_t)l * DD,
                                      p_cur, cur_h, cur_l);
    }

    // --- Decoder ---
    launch_sgemm(p_cur, Wdec, bdec, (float*)d_out, MROWS, EE, DD, 0);
}

// round 6
// speedup vs baseline: 4.2762x; 1.3027x over previous
#include <cuda_runtime.h>
#include <cuda_fp16.h>
#include <cstdint>
#include <cstddef>

// ---------------------------------------------------------------------------
// Problem constants
// ---------------------------------------------------------------------------
#define BB   32
#define NN   144
#define EE   127
#define DD   512
#define HH   8
#define DK   64
#define DV   64
#define FF   16384
#define LL   4
#define MROWS (BB*NN)        // 4608
#define KENC  (EE+1)         // 513

// ---------------------------------------------------------------------------
// Scratch (static device globals)
// ---------------------------------------------------------------------------
__device__ float g_xp  [MROWS * KENC];
__device__ float g_xe  [MROWS * DD];
__device__ float g_cur [MROWS * DD];
__device__ float g_qkv [MROWS * 3 * DD];
__device__ float g_q   [MROWS * DD];
__device__ float g_kv  [MROWS * 2 * DD];
__device__ float g_a1  [MROWS * DD];
__device__ float g_a2  [MROWS * DD];
__device__ float g_ao  [MROWS * DD];
__device__ float g_part[2 * MROWS * DD];      // split-K partials

// fp16 activations (hi and, where needed for 2-pass GEMMs, lo)
__device__ __half g_xe_h [MROWS * DD], g_xe_l [MROWS * DD];
__device__ __half g_cur_h[MROWS * DD], g_cur_l[MROWS * DD];
__device__ __half g_qln_h[MROWS * DD], g_qln_l[MROWS * DD];
__device__ __half g_at_h [MROWS * DD], g_at_l [MROWS * DD];
__device__ __half g_a2_h [MROWS * DD];
__device__ __half g_ao_h [MROWS * DD];
__device__ __half g_hid_h[(size_t)MROWS * FF];

// Transposed fp16 weights, [Nrows, K] row-major per layer.
__device__ __half g_wqkvT[(size_t)LL * 3 * DD * DD];
__device__ __half g_woT  [(size_t)LL * DD * DD];
__device__ __half g_w1T  [(size_t)LL * FF * DD];
__device__ __half g_w2T  [(size_t)LL * DD * FF];

// ---------------------------------------------------------------------------
// Small helpers
// ---------------------------------------------------------------------------
__device__ __forceinline__ uint32_t smem_u32(const void* p) {
    uint32_t a;
    asm("{ .reg .u64 t; cvta.to.shared.u64 t, %1; cvt.u32.u64 %0, t; }" : "=r"(a) : "l"(p));
    return a;
}
__device__ __forceinline__ void cpa16(uint32_t d, const void* s) {
    asm volatile("cp.async.cg.shared.global [%0], [%1], 16;" :: "r"(d), "l"(s));
}
__device__ __forceinline__ void cpa_commit() {
    asm volatile("cp.async.commit_group;" ::: "memory");
}
__device__ __forceinline__ void ldsm4(uint32_t a, uint32_t& r0, uint32_t& r1,
                                      uint32_t& r2, uint32_t& r3) {
    asm volatile("ldmatrix.sync.aligned.m8n8.x4.shared.b16 {%0,%1,%2,%3}, [%4];"
                 : "=r"(r0), "=r"(r1), "=r"(r2), "=r"(r3) : "r"(a));
}
__device__ __forceinline__ void mma16816(float* c, const uint32_t* a,
                                         uint32_t b0, uint32_t b1) {
    asm volatile("mma.sync.aligned.m16n8k16.row.col.f32.f16.f16.f32 "
                 "{%0,%1,%2,%3},{%4,%5,%6,%7},{%8,%9},{%0,%1,%2,%3};"
                 : "+f"(c[0]), "+f"(c[1]), "+f"(c[2]), "+f"(c[3])
                 : "r"(a[0]), "r"(a[1]), "r"(a[2]), "r"(a[3]), "r"(b0), "r"(b1));
}
__device__ __forceinline__ void split2(float x, float y, __half2& h, __half2& l) {
    __half hx = __float2half_rn(x);
    __half hy = __float2half_rn(y);
    h = __halves2half2(hx, hy);
    l = __halves2half2(__float2half_rn(x - __half2float(hx)),
                       __float2half_rn(y - __half2float(hy)));
}

// ---------------------------------------------------------------------------
// HMMA fp16 GEMM: C = (Ah [+ Al]) @ Bh^T(stored [N,K])
// TWO=true: 2-pass (A = hi+lo exact). TWO=false: 1-pass (A quantized fp16).
// 128x128x32 tile, 3-stage cp.async pipeline, 256 threads (2M x 4N warps).
// Split-K via gridDim.z: block z computes K-chunk z and writes C + z*M*N.
// Outputs: optional fp32 C, optional fp16 Ch (+ optional Cl).
// Requires M%128==0, N%128==0, (K/gridDim.z)%32==0.
// ---------------------------------------------------------------------------
#define SA    40                    // smem row stride (halves) -> conflict-free ldmatrix
#define TILEB (128 * SA * 2)        // 10240 bytes per tile
#define SMEM_1P (3 * 2 * TILEB)     // 61440
#define SMEM_2P (3 * 3 * TILEB)     // 92160

template<bool TWO>
__global__ void __launch_bounds__(256, 2)
hmma_gemm(const __half* __restrict__ Ah, const __half* __restrict__ Al,
          const __half* __restrict__ Bh,
          const float* __restrict__ bias,
          float* __restrict__ C,
          __half* __restrict__ Ch, __half* __restrict__ Cl,
          int M, int N, int K, int relu)
{
    constexpr uint32_t STAGEB = (TWO ? 3u : 2u) * TILEB;
    const uint32_t OF_A = 0, OF_AL = TILEB, OF_B = TWO ? 2 * TILEB : TILEB;

    extern __shared__ __half smraw[];
    const uint32_t sb = smem_u32(smraw);

    const int tid  = threadIdx.x;
    const int lane = tid & 31;
    const int wid  = tid >> 5;
    const int wm   = wid >> 2;
    const int wn   = wid & 3;
    const int bm   = blockIdx.y * 128;
    const int bn   = blockIdx.x * 128;

    const int kc   = K / gridDim.z;
    const int koff = blockIdx.z * kc;
    float* Cz = C ? (C + (size_t)blockIdx.z * M * N) : nullptr;

    // staging: thread covers tile row = tid>>1, 16 halves at col (tid&1)*16
    const int srow = tid >> 1;
    const int scol = (tid & 1) * 16;
    const __half* Ahp = Ah + (size_t)(bm + srow) * K + koff + scol;
    const __half* Alp = TWO ? (Al + (size_t)(bm + srow) * K + koff + scol) : nullptr;
    const __half* Bhp = Bh + (size_t)(bn + srow) * K + koff + scol;
    const uint32_t sts = (uint32_t)(srow * SA + scol) * 2;

    // ldmatrix lane addressing
    const int r  = lane & 7;
    const int q1 = (lane >> 3) & 1;
    const int q2 = lane >> 4;
    const uint32_t oa = (uint32_t)((wm * 64 + q1 * 8 + r) * SA + q2 * 8) * 2;
    const uint32_t ob = (uint32_t)((wn * 32 + q2 * 8 + r) * SA + q1 * 8) * 2;

    float acc[4][4][4];
#pragma unroll
    for (int i = 0; i < 4; i++)
#pragma unroll
        for (int j = 0; j < 4; j++)
#pragma unroll
            for (int t = 0; t < 4; t++) acc[i][j][t] = 0.f;

    const int niter = kc / 32;

    auto load_stage = [&](int j) {
        const uint32_t so = (uint32_t)(j % 3) * STAGEB;
        const size_t ko = (size_t)j * 32;
        cpa16(sb + so + OF_A + sts,      Ahp + ko);
        cpa16(sb + so + OF_A + sts + 16, Ahp + ko + 8);
        if (TWO) {
            cpa16(sb + so + OF_AL + sts,      Alp + ko);
            cpa16(sb + so + OF_AL + sts + 16, Alp + ko + 8);
        }
        cpa16(sb + so + OF_B + sts,      Bhp + ko);
        cpa16(sb + so + OF_B + sts + 16, Bhp + ko + 8);
        cpa_commit();
    };

    load_stage(0);
    if (niter > 1) load_stage(1);

    for (int i = 0; i < niter; i++) {
        if (i + 1 < niter) asm volatile("cp.async.wait_group 1;" ::: "memory");
        else               asm volatile("cp.async.wait_group 0;" ::: "memory");
        __syncthreads();

        const uint32_t so = (uint32_t)(i % 3) * STAGEB;
#pragma unroll
        for (int ks = 0; ks < 2; ks++) {
            const uint32_t ko = (uint32_t)ks * 32;
            uint32_t ah[4][4], bhf[2][4];
#pragma unroll
            for (int mi = 0; mi < 4; mi++) {
                const uint32_t aoff = oa + (uint32_t)(mi * 16 * SA) * 2 + ko;
                ldsm4(sb + so + OF_A + aoff, ah[mi][0], ah[mi][1], ah[mi][2], ah[mi][3]);
            }
#pragma unroll
            for (int p = 0; p < 2; p++) {
                const uint32_t boff = ob + (uint32_t)(p * 16 * SA) * 2 + ko;
                ldsm4(sb + so + OF_B + boff, bhf[p][0], bhf[p][1], bhf[p][2], bhf[p][3]);
            }
#pragma unroll
            for (int mi = 0; mi < 4; mi++)
#pragma unroll
                for (int ni = 0; ni < 4; ni++) {
                    const int p = ni >> 1, e = (ni & 1) * 2;
                    mma16816(acc[mi][ni], ah[mi], bhf[p][e], bhf[p][e + 1]);
                }
            if (TWO) {
                uint32_t al[4][4];
#pragma unroll
                for (int mi = 0; mi < 4; mi++) {
                    const uint32_t aoff = oa + (uint32_t)(mi * 16 * SA) * 2 + ko;
                    ldsm4(sb + so + OF_AL + aoff, al[mi][0], al[mi][1], al[mi][2], al[mi][3]);
                }
#pragma unroll
                for (int mi = 0; mi < 4; mi++)
#pragma unroll
                    for (int ni = 0; ni < 4; ni++) {
                        const int p = ni >> 1, e = (ni & 1) * 2;
                        mma16816(acc[mi][ni], al[mi], bhf[p][e], bhf[p][e + 1]);
                    }
            }
        }
        if (i + 2 < niter) load_stage(i + 2);
    }

    // ---- epilogue ----
    const int erow = lane >> 2;
    const int ecol = (lane & 3) * 2;
#pragma unroll
    for (int mi = 0; mi < 4; mi++) {
        const int gr = bm + wm * 64 + mi * 16 + erow;
#pragma unroll
        for (int ni = 0; ni < 4; ni++) {
            const int gc = bn + wn * 32 + ni * 8 + ecol;
            float2 v0 = make_float2(acc[mi][ni][0], acc[mi][ni][1]);
            float2 v1 = make_float2(acc[mi][ni][2], acc[mi][ni][3]);
            if (bias) {
                float bx = bias[gc], by = bias[gc + 1];
                v0.x += bx; v0.y += by; v1.x += bx; v1.y += by;
            }
            if (relu) {
                v0.x = fmaxf(v0.x, 0.f); v0.y = fmaxf(v0.y, 0.f);
                v1.x = fmaxf(v1.x, 0.f); v1.y = fmaxf(v1.y, 0.f);
            }
            const size_t o0 = (size_t)gr * N + gc;
            const size_t o1 = (size_t)(gr + 8) * N + gc;
            if (Cz) {
                *(float2*)(Cz + o0) = v0;
                *(float2*)(Cz + o1) = v1;
            }
            if (Ch) {
                __half2 h0, l0, h1, l1;
                split2(v0.x, v0.y, h0, l0);
                split2(v1.x, v1.y, h1, l1);
                *(__half2*)(Ch + o0) = h0;
                *(__half2*)(Ch + o1) = h1;
                if (Cl) {
                    *(__half2*)(Cl + o0) = l0;
                    *(__half2*)(Cl + o1) = l1;
                }
            }
        }
    }
}

// ---------------------------------------------------------------------------
// Weight transpose + fp16 convert: W[K,N] fp32 -> Th [rowOff+n, k] fp16.
// ---------------------------------------------------------------------------
__global__ void wconv_kernel(const float* __restrict__ W,
                             __half* __restrict__ Th,
                             int K, int N,
                             size_t inLS, size_t outLS, int rowOff)
{
    __shared__ float t[32][33];
    const float* Wz = W + (size_t)blockIdx.z * inLS;
    __half* Thz = Th + (size_t)blockIdx.z * outLS;
    const int n0 = blockIdx.x * 32, k0 = blockIdx.y * 32;
    const int tx = threadIdx.x, ty = threadIdx.y;
#pragma unroll
    for (int i = 0; i < 32; i += 8)
        t[ty + i][tx] = Wz[(size_t)(k0 + ty + i) * N + n0 + tx];
    __syncthreads();
#pragma unroll
    for (int i = 0; i < 32; i += 8) {
        float f = t[tx][ty + i];
        Thz[(size_t)(rowOff + n0 + ty + i) * K + k0 + tx] = __float2half_rn(f);
    }
}

// ---------------------------------------------------------------------------
// Elementwise fp32 -> fp16 hi/lo split
// ---------------------------------------------------------------------------
__global__ void split_kernel(const float* __restrict__ x,
                             __half* __restrict__ h, __half* __restrict__ l, int n)
{
    int i = (blockIdx.x * 256 + threadIdx.x) * 4;
    if (i >= n) return;
    float4 f = *(const float4*)(x + i);
    __half2 h0, l0, h1, l1;
    split2(f.x, f.y, h0, l0);
    split2(f.z, f.w, h1, l1);
    *(__half2*)(h + i)     = h0;
    *(__half2*)(h + i + 2) = h1;
    *(__half2*)(l + i)     = l0;
    *(__half2*)(l + i + 2) = l1;
}

// ---------------------------------------------------------------------------
// Fallback fp32 SGEMM (encoder K=513, decoder N=127)
// ---------------------------------------------------------------------------
#define BM 128
#define BN 128
#define BK 16

__global__ void __launch_bounds__(256)
sgemm_kernel(const float* __restrict__ A, const float* __restrict__ B,
             const float* __restrict__ bias, float* __restrict__ C,
             int M, int N, int K, int relu)
{
    __shared__ __align__(16) float As[BK][BM];
    __shared__ __align__(16) float Bs[BK][BN];

    const int tid = threadIdx.x;
    const int tx = tid & 15, ty = tid >> 4;
    const int bm = blockIdx.y * BM, bn = blockIdx.x * BN;

    float acc[8][8];
#pragma unroll
    for (int i = 0; i < 8; i++)
#pragma unroll
        for (int j = 0; j < 8; j++) acc[i][j] = 0.f;

    for (int k0 = 0; k0 < K; k0 += BK) {
#pragma unroll
        for (int i = tid; i < BM * BK; i += 256) {
            int m = i >> 4, kk = i & 15;
            int gm = bm + m, gk = k0 + kk;
            As[kk][m] = (gm < M && gk < K) ? A[(size_t)gm * K + gk] : 0.f;
        }
#pragma unroll
        for (int i = tid; i < BK * BN; i += 256) {
            int kk = i >> 7, n = i & 127;
            int gk = k0 + kk, gn = bn + n;
            Bs[kk][n] = (gk < K && gn < N) ? B[(size_t)gk * N + gn] : 0.f;
        }
        __syncthreads();
#pragma unroll
        for (int kk = 0; kk < BK; kk++) {
            float4 a0 = *(const float4*)&As[kk][ty * 4];
            float4 a1 = *(const float4*)&As[kk][ty * 4 + 64];
            float4 b0 = *(const float4*)&Bs[kk][tx * 4];
            float4 b1 = *(const float4*)&Bs[kk][tx * 4 + 64];
            float arr[8] = {a0.x, a0.y, a0.z, a0.w, a1.x, a1.y, a1.z, a1.w};
            float brr[8] = {b0.x, b0.y, b0.z, b0.w, b1.x, b1.y, b1.z, b1.w};
#pragma unroll
            for (int i = 0; i < 8; i++)
#pragma unroll
                for (int j = 0; j < 8; j++)
                    acc[i][j] += arr[i] * brr[j];
        }
        __syncthreads();
    }
#pragma unroll
    for (int i = 0; i < 8; i++) {
        int lm = (i < 4) ? (ty * 4 + i) : (64 + ty * 4 + i - 4);
        int gm = bm + lm;
        if (gm >= M) continue;
#pragma unroll
        for (int j = 0; j < 8; j++) {
            int ln = (j < 4) ? (tx * 4 + j) : (64 + tx * 4 + j - 4);
            int gn = bn + ln;
            if (gn >= N) continue;
            float val = acc[i][j];
            if (bias) val += bias[gn];
            if (relu) val = fmaxf(val, 0.f);
            C[(size_t)gm * N + gn] = val;
        }
    }
}

// ---------------------------------------------------------------------------
// Positional-encoding concat
// ---------------------------------------------------------------------------
__global__ void concat_pe_kernel(const float* __restrict__ x, float* __restrict__ xp)
{
    int idx = blockIdx.x * 256 + threadIdx.x;
    if (idx >= MROWS * KENC) return;
    int row = idx / KENC;
    int c = idx - row * KENC;
    float val;
    if (c < EE) val = x[(size_t)row * EE + c];
    else        val = (float)(row % NN) * (1.f / (float)(NN - 1));
    xp[idx] = val;
}

// ---------------------------------------------------------------------------
// Diagonal-softmax attention; emits fp16 hi/lo split output (row stride DD).
// ---------------------------------------------------------------------------
__global__ void __launch_bounds__(256)
diag_attn_kernel(const float* __restrict__ q, int ldq,
                 const float* __restrict__ k, int ldk,
                 const float* __restrict__ v, int ldv,
                 __half* __restrict__ oh, __half* __restrict__ ol, int masked)
{
    const int n = blockIdx.x, h = blockIdx.y, b = blockIdx.z;
    const int t = threadIdx.x;

    __shared__ float qs[DK];
    __shared__ float sc[256];
    __shared__ float red[256];

    const int row = b * NN + n;
    const int hoff = h * DK;
    if (t < DK) qs[t] = q[(size_t)row * ldq + hoff + t];
    __syncthreads();

    const int mlim = masked ? (n + 1) : NN;
    float s = 0.f;
    if (t < mlim) {
        const float* kr = k + (size_t)(b * NN + t) * ldk + hoff;
#pragma unroll
        for (int d = 0; d < DK; d++) s += qs[d] * kr[d];
    }
    sc[t] = s;
    red[t] = (t < mlim) ? s : -3.0e38f;
    __syncthreads();
#pragma unroll
    for (int off = 128; off > 0; off >>= 1) {
        if (t < off) red[t] = fmaxf(red[t], red[t + off]);
        __syncthreads();
    }
    const float mx = red[0];
    __syncthreads();
    red[t] = (t < mlim) ? expf(sc[t] - mx) : 0.f;
    __syncthreads();
#pragma unroll
    for (int off = 128; off > 0; off >>= 1) {
        if (t < off) red[t] += red[t + off];
        __syncthreads();
    }
    const float denom = red[0];
    const float dcoef = expf(sc[n] - mx) / denom;

    if (t < DV) {
        const float val = dcoef * v[(size_t)row * ldv + hoff + t];
        __half hx = __float2half_rn(val);
        oh[(size_t)row * DD + hoff + t] = hx;
        ol[(size_t)row * DD + hoff + t] = __float2half_rn(val - __half2float(hx));
    }
}

// ---------------------------------------------------------------------------
// Fused (optional partial-sum + bias) residual add + LayerNorm (D=512).
// x = a + (a2?) + (bias?) ; y = LN(x + r). Emits fp32 out?, fp16 oh?, ol?.
// ---------------------------------------------------------------------------
__global__ void __launch_bounds__(256)
add_ln_kernel(const float* __restrict__ a, const float* __restrict__ a2,
              const float* __restrict__ bias,
              const float* __restrict__ r,
              const float* __restrict__ g, const float* __restrict__ beta,
              float* __restrict__ out,
              __half* __restrict__ oh, __half* __restrict__ ol)
{
    const int row = blockIdx.x;
    const int t = threadIdx.x;
    __shared__ float red[256];

    const size_t base = (size_t)row * DD;
    float x0 = a[base + t]       + r[base + t];
    float x1 = a[base + 256 + t] + r[base + 256 + t];
    if (a2)   { x0 += a2[base + t]; x1 += a2[base + 256 + t]; }
    if (bias) { x0 += bias[t];      x1 += bias[256 + t]; }

    red[t] = x0 + x1;
    __syncthreads();
#pragma unroll
    for (int off = 128; off > 0; off >>= 1) {
        if (t < off) red[t] += red[t + off];
        __syncthreads();
    }
    const float mean = red[0] * (1.f / (float)DD);
    __syncthreads();
    const float d0 = x0 - mean, d1 = x1 - mean;
    red[t] = d0 * d0 + d1 * d1;
    __syncthreads();
#pragma unroll
    for (int off = 128; off > 0; off >>= 1) {
        if (t < off) red[t] += red[t + off];
        __syncthreads();
    }
    const float inv = rsqrtf(red[0] * (1.f / (float)DD) + 1e-5f);

    const float y0 = d0 * inv * g[t]       + beta[t];
    const float y1 = d1 * inv * g[256 + t] + beta[256 + t];
    if (out) {
        out[base + t]       = y0;
        out[base + 256 + t] = y1;
    }
    if (oh) {
        __half h0 = __float2half_rn(y0);
        __half h1 = __float2half_rn(y1);
        oh[base + t]       = h0;
        oh[base + 256 + t] = h1;
        if (ol) {
            ol[base + t]       = __float2half_rn(y0 - __half2float(h0));
            ol[base + 256 + t] = __float2half_rn(y1 - __half2float(h1));
        }
    }
}

// ---------------------------------------------------------------------------
// Host orchestration
// ---------------------------------------------------------------------------
static inline void launch_sgemm(const float* A, const float* B, const float* bias,
                                float* C, int M, int N, int K, int relu)
{
    dim3 grid((N + BN - 1) / BN, (M + BM - 1) / BM);
    sgemm_kernel<<<grid, 256>>>(A, B, bias, C, M, N, K, relu);
}

// 2-pass (A exact via hi+lo)
static inline void hgemm2(const __half* Ah, const __half* Al, const __half* Bh,
                          const float* bias, float* C, __half* Ch, __half* Cl,
                          int M, int N, int K, int relu)
{
    dim3 grid(N / 128, M / 128, 1);
    hmma_gemm<true><<<grid, 256, SMEM_2P>>>(Ah, Al, Bh, bias, C, Ch, Cl, M, N, K, relu);
}

// 1-pass (A quantized fp16), optional split-K
static inline void hgemm1(const __half* Ah, const __half* Bh,
                          const float* bias, float* C, __half* Ch,
                          int M, int N, int K, int relu, int splitk)
{
    dim3 grid(N / 128, M / 128, splitk);
    hmma_gemm<false><<<grid, 256, SMEM_1P>>>(Ah, nullptr, Bh, bias, C, Ch, nullptr,
                                             M, N, K, relu);
}

extern "C" void kernel_launch(void* const* d_in, const int* in_sizes, int n_in,
                              void* d_out, int out_size)
{
    const float* x    = (const float*)d_in[1];
    const float* Wenc = (const float*)d_in[3];
    const float* benc = (const float*)d_in[4];
    const float* Wq   = (const float*)d_in[5];
    const float* Wk   = (const float*)d_in[6];
    const float* Wv   = (const float*)d_in[7];
    const float* Wo   = (const float*)d_in[8];
    const float* bo   = (const float*)d_in[9];
    const float* ln1g = (const float*)d_in[10];
    const float* ln1b = (const float*)d_in[11];
    const float* ln2g = (const float*)d_in[12];
    const float* ln2b = (const float*)d_in[13];
    const float* ln3g = (const float*)d_in[14];
    const float* ln3b = (const float*)d_in[15];
    const float* W1   = (const float*)d_in[16];
    const float* b1   = (const float*)d_in[17];
    const float* W2   = (const float*)d_in[18];
    const float* b2   = (const float*)d_in[19];
    const float* Wdec = (const float*)d_in[20];
    const float* bdec = (const float*)d_in[21];

    float *p_xp, *p_xe, *p_cur, *p_qkv, *p_q, *p_kv, *p_a1, *p_a2, *p_ao, *p_part;
    cudaGetSymbolAddress((void**)&p_xp,   g_xp);
    cudaGetSymbolAddress((void**)&p_xe,   g_xe);
    cudaGetSymbolAddress((void**)&p_cur,  g_cur);
    cudaGetSymbolAddress((void**)&p_qkv,  g_qkv);
    cudaGetSymbolAddress((void**)&p_q,    g_q);
    cudaGetSymbolAddress((void**)&p_kv,   g_kv);
    cudaGetSymbolAddress((void**)&p_a1,   g_a1);
    cudaGetSymbolAddress((void**)&p_a2,   g_a2);
    cudaGetSymbolAddress((void**)&p_ao,   g_ao);
    cudaGetSymbolAddress((void**)&p_part, g_part);

    __half *xe_h, *xe_l, *cur_h, *cur_l, *qln_h, *qln_l, *at_h, *at_l,
           *a2_h, *ao_h, *hid_h;
    cudaGetSymbolAddress((void**)&xe_h,  g_xe_h);
    cudaGetSymbolAddress((void**)&xe_l,  g_xe_l);
    cudaGetSymbolAddress((void**)&cur_h, g_cur_h);
    cudaGetSymbolAddress((void**)&cur_l, g_cur_l);
    cudaGetSymbolAddress((void**)&qln_h, g_qln_h);
    cudaGetSymbolAddress((void**)&qln_l, g_qln_l);
    cudaGetSymbolAddress((void**)&at_h,  g_at_h);
    cudaGetSymbolAddress((void**)&at_l,  g_at_l);
    cudaGetSymbolAddress((void**)&a2_h,  g_a2_h);
    cudaGetSymbolAddress((void**)&ao_h,  g_ao_h);
    cudaGetSymbolAddress((void**)&hid_h, g_hid_h);

    __half *wqkv, *wo, *w1, *w2;
    cudaGetSymbolAddress((void**)&wqkv, g_wqkvT);
    cudaGetSymbolAddress((void**)&wo,   g_woT);
    cudaGetSymbolAddress((void**)&w1,   g_w1T);
    cudaGetSymbolAddress((void**)&w2,   g_w2T);

    cudaFuncSetAttribute(hmma_gemm<true>,  cudaFuncAttributeMaxDynamicSharedMemorySize, SMEM_2P);
    cudaFuncSetAttribute(hmma_gemm<false>, cudaFuncAttributeMaxDynamicSharedMemorySize, SMEM_1P);

    // --- Weight transpose + fp16 convert ---
    {
        dim3 wb(32, 8);
        const size_t dd2 = (size_t)DD * DD;
        wconv_kernel<<<dim3(DD/32, DD/32, LL), wb>>>(Wq, wqkv, DD, DD, dd2, 3*dd2, 0);
        wconv_kernel<<<dim3(DD/32, DD/32, LL), wb>>>(Wk, wqkv, DD, DD, dd2, 3*dd2, DD);
        wconv_kernel<<<dim3(DD/32, DD/32, LL), wb>>>(Wv, wqkv, DD, DD, dd2, 3*dd2, 2*DD);
        wconv_kernel<<<dim3(DD/32, DD/32, LL), wb>>>(Wo, wo, DD, DD, dd2, dd2, 0);
        const size_t df = (size_t)DD * FF;
        wconv_kernel<<<dim3(FF/32, DD/32, LL), wb>>>(W1, w1, DD, FF, df, df, 0);
        wconv_kernel<<<dim3(DD/32, FF/32, LL), wb>>>(W2, w2, FF, DD, df, df, 0);
    }

    // --- Encoder + split ---
    {
        int tot = MROWS * KENC;
        concat_pe_kernel<<<(tot + 255) / 256, 256>>>(x, p_xp);
        launch_sgemm(p_xp, Wenc, benc, p_xe, MROWS, DD, KENC, 0);
        int n = MROWS * DD;
        split_kernel<<<(n / 4 + 255) / 256, 256>>>(p_xe, xe_h, xe_l, n);
    }

    dim3 attn_grid(NN, HH, BB);
    float* part1 = p_part + (size_t)MROWS * DD;

    for (int l = 0; l < LL; l++) {
        const __half* in_h = (l == 0) ? xe_h : cur_h;
        const __half* in_l = (l == 0) ? xe_l : cur_l;
        const __half* wqkv_l = wqkv + (size_t)l * 3 * DD * DD;
        const __half* wkv_l  = wqkv_l + (size_t)DD * DD;
        const __half* wo_l   = wo + (size_t)l * DD * DD;
        const __half* w1_l   = w1 + (size_t)l * DD * FF;
        const __half* w2_l   = w2 + (size_t)l * DD * FF;
        const float* bol = bo + (size_t)l * DD;
        const float* b1l = b1 + (size_t)l * FF;
        const float* b2l = b2 + (size_t)l * DD;

        // --- MHA1 (causal): fused QKV projection (2-pass) ---
        hgemm2(in_h, in_l, wqkv_l, nullptr, p_qkv, nullptr, nullptr,
               MROWS, 3 * DD, DD, 0);
        diag_attn_kernel<<<attn_grid, 256>>>(p_qkv, 3 * DD,
                                             p_qkv + DD, 3 * DD,
                                             p_qkv + 2 * DD, 3 * DD, at_h, at_l, 1);
        hgemm2(at_h, at_l, wo_l, bol, p_a1, nullptr, nullptr, MROWS, DD, DD, 0);

        // qln = LN(a1 + xe)
        add_ln_kernel<<<MROWS, 256>>>(p_a1, nullptr, nullptr, p_xe,
                                      ln1g + (size_t)l * DD, ln1b + (size_t)l * DD,
                                      nullptr, qln_h, qln_l);

        // --- MHA2 (no mask): Q from qln, K/V from xe (2-pass) ---
        hgemm2(qln_h, qln_l, wqkv_l, nullptr, p_q, nullptr, nullptr,
               MROWS, DD, DD, 0);
        hgemm2(xe_h, xe_l, wkv_l, nullptr, p_kv, nullptr, nullptr,
               MROWS, 2 * DD, DD, 0);
        diag_attn_kernel<<<attn_grid, 256>>>(p_q, DD,
                                             p_kv, 2 * DD,
                                             p_kv + DD, 2 * DD, at_h, at_l, 0);
        hgemm2(at_h, at_l, wo_l, bol, p_a2, a2_h, nullptr, MROWS, DD, DD, 0);

        // --- FF stack 1 (1-pass fp16; W2 split-K=2, combined in add_ln) ---
        hgemm1(a2_h, w1_l, b1l, nullptr, hid_h, MROWS, FF, DD, 1, 1);
        hgemm1(hid_h, w2_l, nullptr, p_part, nullptr, MROWS, DD, FF, 0, 2);
        add_ln_kernel<<<MROWS, 256>>>(p_part, part1, b2l, p_a2,
                                      ln2g + (size_t)l * DD, ln2b + (size_t)l * DD,
                                      p_ao, ao_h, nullptr);

        // --- FF stack 2 ---
        hgemm1(ao_h, w1_l, b1l, nullptr, hid_h, MROWS, FF, DD, 1, 1);
        hgemm1(hid_h, w2_l, nullptr, p_part, nullptr, MROWS, DD, FF, 0, 2);
        add_ln_kernel<<<MROWS, 256>>>(p_part, part1, b2l, p_ao,
                                      ln3g + (size_t)l * DD, ln3b + (size_t)l * DD,
                                      p_cur, cur_h, cur_l);
    }

    // --- Decoder ---
    launch_sgemm(p_cur, Wdec, bdec, (float*)d_out, MROWS, EE, DD, 0);
}